// round 7
// baseline (speedup 1.0000x reference)
#include <cuda_runtime.h>
#include <cuda_fp16.h>
#include <cstdint>
#include <mma.h>

using namespace nvcuda;

#define BATCH 128
#define SEQ   512
#define IDIM  256
#define HDIM  512
#define GDIM  2048   // 4*H

// ---------------- device scratch (static: allocation-guard safe) ----------------
__device__ __half g_xg[2][SEQ][BATCH][GDIM];     // precomputed input-side gates, fp16 (512 MB)
__device__ __half g_h[2][2][BATCH][HDIM];        // ping-pong recurrent hidden state (fp16)
__device__ __half g_Wih[GDIM][IDIM];             // fp16 converted weights
__device__ __half g_Whh[GDIM][HDIM];
__device__ float  g_bias[GDIM];                  // b_ih + b_hh
__device__ unsigned g_flag[8][32];               // per-group step flags: word[slice] = steps published

// ---------------- prep: fp32->fp16 weight convert, bias combine, flag reset ----------------
__global__ void prep_kernel(const float* __restrict__ Wih, const float* __restrict__ Whh,
                            const float* __restrict__ bih, const float* __restrict__ bhh) {
    int idx = blockIdx.x * blockDim.x + threadIdx.x;          // grid covers 1048576
    if (idx < GDIM * IDIM) (&g_Wih[0][0])[idx] = __float2half(Wih[idx]);
    if (idx < GDIM * HDIM) (&g_Whh[0][0])[idx] = __float2half(Whh[idx]);
    if (idx < GDIM)        g_bias[idx] = bih[idx] + bhh[idx];
    if (idx < 256)         (&g_flag[0][0])[idx] = 0u;
}

// ---------------- input projection GEMM: xg[text][s][b][g] = x[b,s,:] @ W_ih[g,:] + bias[g] ----------------
__global__ void __launch_bounds__(256) xgemm_kernel(const float* __restrict__ x0,
                                                    const float* __restrict__ x1) {
    extern __shared__ char sm[];
    half  (*Xs)[72]  = (half (*)[72])sm;                            // 64 x 72 fp16
    half  (*Ws)[72]  = (half (*)[72])(sm + 64 * 72 * 2);            // 256 x 72 fp16
    float (*Os)[260] = (float(*)[260])(sm + 64 * 72 * 2 + 256 * 72 * 2); // 64 x 260 f32

    const int text = blockIdx.z;
    const float* __restrict__ x = text ? x1 : x0;
    const int n0 = blockIdx.x * 256;
    const int rt = blockIdx.y;
    const int s  = rt >> 1;
    const int b0 = (rt & 1) * 64;
    const int tid = threadIdx.x;
    const int w   = tid >> 5;
    const int wm  = (w & 1) * 32;
    const int wn  = (w >> 1) * 64;

    wmma::fragment<wmma::accumulator, 16, 16, 16, float> acc[2][4];
#pragma unroll
    for (int i = 0; i < 2; i++)
#pragma unroll
        for (int j = 0; j < 4; j++) wmma::fill_fragment(acc[i][j], 0.0f);

    for (int kc = 0; kc < IDIM; kc += 64) {
        {
            int r  = tid >> 2;
            int c0 = (tid & 3) * 16;
            const float4* src = (const float4*)(x + (size_t)(b0 + r) * (SEQ * IDIM) + (size_t)s * IDIM + kc + c0);
#pragma unroll
            for (int v = 0; v < 4; v++) {
                float4 f = src[v];
                half2* d = (half2*)&Xs[r][c0 + v * 4];
                d[0] = __floats2half2_rn(f.x, f.y);
                d[1] = __floats2half2_rn(f.z, f.w);
            }
        }
        {
            const uint4* src = (const uint4*)(&g_Wih[n0 + tid][kc]);
            uint4* dst = (uint4*)(&Ws[tid][0]);
#pragma unroll
            for (int v = 0; v < 8; v++) dst[v] = src[v];
        }
        __syncthreads();
#pragma unroll
        for (int kk = 0; kk < 4; kk++) {
            wmma::fragment<wmma::matrix_a, 16, 16, 16, half, wmma::row_major> af[2];
            wmma::load_matrix_sync(af[0], &Xs[wm][kk * 16], 72);
            wmma::load_matrix_sync(af[1], &Xs[wm + 16][kk * 16], 72);
#pragma unroll
            for (int nt = 0; nt < 4; nt++) {
                wmma::fragment<wmma::matrix_b, 16, 16, 16, half, wmma::col_major> bf;
                wmma::load_matrix_sync(bf, &Ws[wn + nt * 16][kk * 16], 72);
                wmma::mma_sync(acc[0][nt], af[0], bf, acc[0][nt]);
                wmma::mma_sync(acc[1][nt], af[1], bf, acc[1][nt]);
            }
        }
        __syncthreads();
    }
#pragma unroll
    for (int i = 0; i < 2; i++)
#pragma unroll
        for (int nt = 0; nt < 4; nt++)
            wmma::store_matrix_sync(&Os[wm + i * 16][wn + nt * 16], acc[i][nt], 260, wmma::mem_row_major);
    __syncthreads();

#pragma unroll
    for (int v = 0; v < 16; v++) {
        int lin = v * 256 + tid;
        int r = lin >> 6;
        int c = (lin & 63) * 4;
        int R = rt * 64 + r;                 // == s*128 + b
        half2 o0 = __floats2half2_rn(Os[r][c + 0] + g_bias[n0 + c + 0],
                                     Os[r][c + 1] + g_bias[n0 + c + 1]);
        half2 o1 = __floats2half2_rn(Os[r][c + 2] + g_bias[n0 + c + 2],
                                     Os[r][c + 3] + g_bias[n0 + c + 3]);
        half2* dst = (half2*)((&g_xg[0][0][0][0]) + ((size_t)text * 65536 + R) * GDIM + n0 + c);
        dst[0] = o0;
        dst[1] = o1;
    }
}

// ---------------- recurrence: 8 independent groups x 16 CTAs, L2 h exchange ----------------
__device__ __forceinline__ uint32_t smem_u32(const void* p) {
    uint32_t a;
    asm("{ .reg .u64 t; cvta.to.shared.u64 t, %1; cvt.u32.u64 %0, t; }" : "=r"(a) : "l"(p));
    return a;
}

__device__ __forceinline__ float fast_sigmoid(float x) {
    return __fdividef(1.0f, 1.0f + __expf(-x));          // MUFU.EX2 + MUFU.RCP path
}
__device__ __forceinline__ float fast_tanh(float x) {
    return 1.0f - __fdividef(2.0f, 1.0f + __expf(2.0f * x));
}

__global__ void __launch_bounds__(256) lstm_rec_kernel(float* __restrict__ out) {
    extern __shared__ char sm[];
    half  (*Wsh)[520] = (half (*)[520])sm;                       // 128 x 520  (133120 B)
    half  (*Ash)[520] = (half (*)[520])(sm + 133120);            // 32 x 520   (33280 B)
    float (*Gsh)[132] = (float(*)[132])(sm + 133120 + 33280);    // 32 x 132   (16896 B)

    const int bx    = blockIdx.x;
    const int text  = bx >> 6;
    const int chunk = (bx >> 4) & 3;
    const int slice = bx & 15;
    const int grp   = bx >> 4;           // 0..7
    const int tid   = threadIdx.x;
    const int w     = tid >> 5;
    const int wm    = (w & 1) * 16;      // warp M offset (0/16)
    const int nq    = w >> 1;            // gate index (0..3), 32 local cols

    // elementwise ownership: each thread owns row b, 4 consecutive cols j0..j0+3
    const int b  = tid >> 3;
    const int j0 = (tid & 7) * 4;
    float creg[4] = {0.f, 0.f, 0.f, 0.f};

    unsigned* const flags  = &g_flag[grp][0];
    unsigned* const myflag = &g_flag[grp][slice];

    // load persistent W_hh slice: local row r -> global gate row (r>>5)*512 + slice*32 + (r&31)
#pragma unroll
    for (int v = 0; v < 32; v++) {
        int lin = v * 256 + tid;
        int r = lin >> 6, u = lin & 63;
        int grow = (r >> 5) * HDIM + slice * 32 + (r & 31);
        ((uint4*)&Wsh[r][0])[u] = ((const uint4*)&g_Whh[grow][0])[u];
    }
    // zero own h(0) slice in ping 0
    if (tid < 128) {
        int r = tid >> 2, u = tid & 3;
        ((uint2*)&g_h[0][text][chunk * 32 + r][slice * 32])[u] = make_uint2(0, 0);
    }
    __syncthreads();
    if (tid == 0) {
        asm volatile("fence.acq_rel.gpu;" ::: "memory");
        asm volatile("st.relaxed.gpu.global.u32 [%0], %1;" :: "l"(myflag), "r"(1u) : "memory");
    }

    int p = 0;

    for (int t = 0; t < SEQ; t++) {
        const unsigned need = (unsigned)(t + 1);

        // ---- prefetch input-side gates (function of t only; in flight across the wait) ----
        const __half* xbase = &g_xg[text][t][chunk * 32 + b][slice * 32 + j0];
        uint2 xi2 = *(const uint2*)(xbase + 0 * HDIM);
        uint2 xf2 = *(const uint2*)(xbase + 1 * HDIM);
        uint2 xg2 = *(const uint2*)(xbase + 2 * HDIM);
        uint2 xo2 = *(const uint2*)(xbase + 3 * HDIM);

        // ---- barrier: wait until all 16 CTAs published h(t) ----
        if (tid == 0) {
            for (;;) {
                unsigned a0, a1, a2, a3, b0_, b1_, b2_, b3_;
                asm volatile("ld.volatile.global.v4.u32 {%0,%1,%2,%3}, [%4];"
                             : "=r"(a0), "=r"(a1), "=r"(a2), "=r"(a3) : "l"(flags));
                asm volatile("ld.volatile.global.v4.u32 {%0,%1,%2,%3}, [%4];"
                             : "=r"(b0_), "=r"(b1_), "=r"(b2_), "=r"(b3_) : "l"(flags + 4));
                unsigned c0_, c1_, c2_, c3_, d0, d1, d2, d3;
                asm volatile("ld.volatile.global.v4.u32 {%0,%1,%2,%3}, [%4];"
                             : "=r"(c0_), "=r"(c1_), "=r"(c2_), "=r"(c3_) : "l"(flags + 8));
                asm volatile("ld.volatile.global.v4.u32 {%0,%1,%2,%3}, [%4];"
                             : "=r"(d0), "=r"(d1), "=r"(d2), "=r"(d3) : "l"(flags + 12));
                unsigned m = min(min(min(a0, a1), min(a2, a3)), min(min(b0_, b1_), min(b2_, b3_)));
                m = min(m, min(min(min(c0_, c1_), min(c2_, c3_)), min(min(d0, d1), min(d2, d3))));
                if (m >= need) break;
            }
            asm volatile("fence.acq_rel.gpu;" ::: "memory");
        }
        __syncthreads();

        // ---- issue cp.async of full h chunk [32 x 512] in 4 K-chunks of 128 cols ----
        const __half* hsrc = &g_h[p][text][chunk * 32][0];
#pragma unroll
        for (int c = 0; c < 4; c++) {
#pragma unroll
            for (int it = 0; it < 2; it++) {
                int lin = it * 256 + tid;          // 0..511
                int r = lin >> 4, u = lin & 15;
                uint32_t dst = smem_u32(&Ash[r][c * 128 + u * 8]);
                const __half* src = hsrc + (size_t)r * HDIM + c * 128 + u * 8;
                asm volatile("cp.async.cg.shared.global [%0], [%1], 16;" :: "r"(dst), "l"(src) : "memory");
            }
            asm volatile("cp.async.commit_group;" ::: "memory");
        }

        // ---- GEMM: gates[32 x 128] = h[32 x 512] @ Whh_slice^T, overlapped with cp.async ----
        wmma::fragment<wmma::accumulator, 16, 16, 16, float> accA[2], accB[2];
        wmma::fill_fragment(accA[0], 0.0f); wmma::fill_fragment(accA[1], 0.0f);
        wmma::fill_fragment(accB[0], 0.0f); wmma::fill_fragment(accB[1], 0.0f);

#define GEMM_CHUNK(CIDX, WG, ACC)                                                          \
        asm volatile("cp.async.wait_group %0;" :: "n"(WG) : "memory");                     \
        __syncthreads();                                                                   \
        _Pragma("unroll")                                                                  \
        for (int kk = (CIDX) * 8; kk < (CIDX) * 8 + 8; kk++) {                             \
            wmma::fragment<wmma::matrix_a, 16, 16, 16, half, wmma::row_major> af;          \
            wmma::load_matrix_sync(af, &Ash[wm][kk * 16], 520);                            \
            wmma::fragment<wmma::matrix_b, 16, 16, 16, half, wmma::col_major> bf;          \
            wmma::load_matrix_sync(bf, &Wsh[nq * 32][kk * 16], 520);                       \
            wmma::mma_sync(ACC[0], af, bf, ACC[0]);                                        \
            wmma::load_matrix_sync(bf, &Wsh[nq * 32 + 16][kk * 16], 520);                  \
            wmma::mma_sync(ACC[1], af, bf, ACC[1]);                                        \
        }

        GEMM_CHUNK(0, 3, accA)
        GEMM_CHUNK(1, 2, accB)
        GEMM_CHUNK(2, 1, accA)
        GEMM_CHUNK(3, 0, accB)
#undef GEMM_CHUNK

#pragma unroll
        for (int k = 0; k < 2; k++) {
#pragma unroll
            for (int i = 0; i < accA[k].num_elements; i++) accA[k].x[i] += accB[k].x[i];
        }
        wmma::store_matrix_sync(&Gsh[wm][nq * 32],      accA[0], 132, wmma::mem_row_major);
        wmma::store_matrix_sync(&Gsh[wm][nq * 32 + 16], accA[1], 132, wmma::mem_row_major);
        __syncthreads();

        // ---- gate nonlinearities + state update: 4 cells per thread (b, j0..j0+3) ----
        float4 iv4 = *(const float4*)&Gsh[b][j0];
        float4 fv4 = *(const float4*)&Gsh[b][32 + j0];
        float4 gv4 = *(const float4*)&Gsh[b][64 + j0];
        float4 ov4 = *(const float4*)&Gsh[b][96 + j0];
        float2 xil = __half22float2(*(const half2*)&xi2.x), xih = __half22float2(*(const half2*)&xi2.y);
        float2 xfl = __half22float2(*(const half2*)&xf2.x), xfh = __half22float2(*(const half2*)&xf2.y);
        float2 xgl = __half22float2(*(const half2*)&xg2.x), xgh = __half22float2(*(const half2*)&xg2.y);
        float2 xol = __half22float2(*(const half2*)&xo2.x), xoh = __half22float2(*(const half2*)&xo2.y);

        float iv[4] = {iv4.x + xil.x, iv4.y + xil.y, iv4.z + xih.x, iv4.w + xih.y};
        float fv[4] = {fv4.x + xfl.x, fv4.y + xfl.y, fv4.z + xfh.x, fv4.w + xfh.y};
        float gv[4] = {gv4.x + xgl.x, gv4.y + xgl.y, gv4.z + xgh.x, gv4.w + xgh.y};
        float ov[4] = {ov4.x + xol.x, ov4.y + xol.y, ov4.z + xoh.x, ov4.w + xoh.y};
        float hv[4];
#pragma unroll
        for (int e = 0; e < 4; e++) {
            float i_ = fast_sigmoid(iv[e]);
            float f_ = fast_sigmoid(fv[e]);
            float g_ = fast_tanh(gv[e]);
            float o_ = fast_sigmoid(ov[e]);
            float c  = f_ * creg[e] + i_ * g_;
            creg[e] = c;
            hv[e] = o_ * fast_tanh(c);
        }

        if (t < SEQ - 1) {
            // publish h(t+1) slice (8B store per thread), then set own flag
            uint2 hp;
            ((half2*)&hp.x)[0] = __floats2half2_rn(hv[0], hv[1]);
            ((half2*)&hp.y)[0] = __floats2half2_rn(hv[2], hv[3]);
            *(uint2*)&g_h[p ^ 1][text][chunk * 32 + b][slice * 32 + j0] = hp;
            __syncthreads();          // all h stores done before the release
            if (tid == 0) {
                asm volatile("fence.acq_rel.gpu;" ::: "memory");
                asm volatile("st.relaxed.gpu.global.u32 [%0], %1;"
                             :: "l"(myflag), "r"(need + 1u) : "memory");
            }
            p ^= 1;
        } else {
            float4 o4 = make_float4(hv[0], hv[1], hv[2], hv[3]);
            *(float4*)&out[((size_t)text * BATCH + chunk * 32 + b) * HDIM + slice * 32 + j0] = o4;
        }
    }
}

// ---------------- launch ----------------
extern "C" void kernel_launch(void* const* d_in, const int* in_sizes, int n_in,
                              void* d_out, int out_size) {
    (void)in_sizes; (void)n_in; (void)out_size;
    const float* x0  = (const float*)d_in[0];
    const float* x1  = (const float*)d_in[1];
    const float* Wih = (const float*)d_in[2];
    const float* Whh = (const float*)d_in[3];
    const float* bih = (const float*)d_in[4];
    const float* bhh = (const float*)d_in[5];
    float* out = (float*)d_out;

    const int REC_SMEM = 133120 + 33280 + 16896;   // 183296
    cudaFuncSetAttribute(xgemm_kernel,    cudaFuncAttributeMaxDynamicSharedMemorySize, 112640);
    cudaFuncSetAttribute(lstm_rec_kernel, cudaFuncAttributeMaxDynamicSharedMemorySize, REC_SMEM);

    prep_kernel<<<4096, 256>>>(Wih, Whh, bih, bhh);
    xgemm_kernel<<<dim3(8, 1024, 2), 256, 112640>>>(x0, x1);
    lstm_rec_kernel<<<128, 256, REC_SMEM>>>(out);
}

// round 8
// speedup vs baseline: 1.3911x; 1.3911x over previous
#include <cuda_runtime.h>
#include <cuda_fp16.h>
#include <cstdint>
#include <mma.h>

using namespace nvcuda;

#define BATCH 128
#define SEQ   512
#define IDIM  256
#define HDIM  512
#define GDIM  2048   // 4*H

// ---------------- device scratch (static: allocation-guard safe) ----------------
__device__ __half g_xg[2][SEQ][BATCH][GDIM];     // precomputed input-side gates, fp16 (512 MB)
__device__ __half g_h[2][2][BATCH][HDIM];        // ping-pong recurrent hidden state (fp16)
__device__ __half g_Wih[GDIM][IDIM];             // fp16 converted weights
__device__ __half g_Whh[GDIM][HDIM];
__device__ float  g_bias[GDIM];                  // b_ih + b_hh
__device__ unsigned g_cnt[8][32];                // per-group barrier counters, 1 per 128B sector

// ---------------- prep: fp32->fp16 weight convert, bias combine, counter reset ----------------
__global__ void prep_kernel(const float* __restrict__ Wih, const float* __restrict__ Whh,
                            const float* __restrict__ bih, const float* __restrict__ bhh) {
    int idx = blockIdx.x * blockDim.x + threadIdx.x;          // grid covers 1048576
    if (idx < GDIM * IDIM) (&g_Wih[0][0])[idx] = __float2half(Wih[idx]);
    if (idx < GDIM * HDIM) (&g_Whh[0][0])[idx] = __float2half(Whh[idx]);
    if (idx < GDIM)        g_bias[idx] = bih[idx] + bhh[idx];
    if (idx < 256)         (&g_cnt[0][0])[idx] = 0u;
}

// ---------------- input projection GEMM: xg[text][s][b][g] = x[b,s,:] @ W_ih[g,:] + bias[g] ----------------
__global__ void __launch_bounds__(256) xgemm_kernel(const float* __restrict__ x0,
                                                    const float* __restrict__ x1) {
    extern __shared__ char sm[];
    half  (*Xs)[72]  = (half (*)[72])sm;                            // 64 x 72 fp16
    half  (*Ws)[72]  = (half (*)[72])(sm + 64 * 72 * 2);            // 256 x 72 fp16
    float (*Os)[260] = (float(*)[260])(sm + 64 * 72 * 2 + 256 * 72 * 2); // 64 x 260 f32

    const int text = blockIdx.z;
    const float* __restrict__ x = text ? x1 : x0;
    const int n0 = blockIdx.x * 256;
    const int rt = blockIdx.y;
    const int s  = rt >> 1;
    const int b0 = (rt & 1) * 64;
    const int tid = threadIdx.x;
    const int w   = tid >> 5;
    const int wm  = (w & 1) * 32;
    const int wn  = (w >> 1) * 64;

    wmma::fragment<wmma::accumulator, 16, 16, 16, float> acc[2][4];
#pragma unroll
    for (int i = 0; i < 2; i++)
#pragma unroll
        for (int j = 0; j < 4; j++) wmma::fill_fragment(acc[i][j], 0.0f);

    for (int kc = 0; kc < IDIM; kc += 64) {
        {
            int r  = tid >> 2;
            int c0 = (tid & 3) * 16;
            const float4* src = (const float4*)(x + (size_t)(b0 + r) * (SEQ * IDIM) + (size_t)s * IDIM + kc + c0);
#pragma unroll
            for (int v = 0; v < 4; v++) {
                float4 f = src[v];
                half2* d = (half2*)&Xs[r][c0 + v * 4];
                d[0] = __floats2half2_rn(f.x, f.y);
                d[1] = __floats2half2_rn(f.z, f.w);
            }
        }
        {
            const uint4* src = (const uint4*)(&g_Wih[n0 + tid][kc]);
            uint4* dst = (uint4*)(&Ws[tid][0]);
#pragma unroll
            for (int v = 0; v < 8; v++) dst[v] = src[v];
        }
        __syncthreads();
#pragma unroll
        for (int kk = 0; kk < 4; kk++) {
            wmma::fragment<wmma::matrix_a, 16, 16, 16, half, wmma::row_major> af[2];
            wmma::load_matrix_sync(af[0], &Xs[wm][kk * 16], 72);
            wmma::load_matrix_sync(af[1], &Xs[wm + 16][kk * 16], 72);
#pragma unroll
            for (int nt = 0; nt < 4; nt++) {
                wmma::fragment<wmma::matrix_b, 16, 16, 16, half, wmma::col_major> bf;
                wmma::load_matrix_sync(bf, &Ws[wn + nt * 16][kk * 16], 72);
                wmma::mma_sync(acc[0][nt], af[0], bf, acc[0][nt]);
                wmma::mma_sync(acc[1][nt], af[1], bf, acc[1][nt]);
            }
        }
        __syncthreads();
    }
#pragma unroll
    for (int i = 0; i < 2; i++)
#pragma unroll
        for (int nt = 0; nt < 4; nt++)
            wmma::store_matrix_sync(&Os[wm + i * 16][wn + nt * 16], acc[i][nt], 260, wmma::mem_row_major);
    __syncthreads();

#pragma unroll
    for (int v = 0; v < 16; v++) {
        int lin = v * 256 + tid;
        int r = lin >> 6;
        int c = (lin & 63) * 4;
        int R = rt * 64 + r;                 // == s*128 + b
        half2 o0 = __floats2half2_rn(Os[r][c + 0] + g_bias[n0 + c + 0],
                                     Os[r][c + 1] + g_bias[n0 + c + 1]);
        half2 o1 = __floats2half2_rn(Os[r][c + 2] + g_bias[n0 + c + 2],
                                     Os[r][c + 3] + g_bias[n0 + c + 3]);
        half2* dst = (half2*)((&g_xg[0][0][0][0]) + ((size_t)text * 65536 + R) * GDIM + n0 + c);
        dst[0] = o0;
        dst[1] = o1;
    }
}

// ---------------- recurrence: 8 independent groups x 16 CTAs, L2 h exchange ----------------
__device__ __forceinline__ uint32_t smem_u32(const void* p) {
    uint32_t a;
    asm("{ .reg .u64 t; cvta.to.shared.u64 t, %1; cvt.u32.u64 %0, t; }" : "=r"(a) : "l"(p));
    return a;
}

__device__ __forceinline__ float fast_sigmoid(float x) {
    return __fdividef(1.0f, 1.0f + __expf(-x));          // MUFU.EX2 + MUFU.RCP path
}
__device__ __forceinline__ float fast_tanh(float x) {
    return 1.0f - __fdividef(2.0f, 1.0f + __expf(2.0f * x));
}

__global__ void __launch_bounds__(256) lstm_rec_kernel(float* __restrict__ out) {
    extern __shared__ char sm[];
    half  (*Wsh)[520] = (half (*)[520])sm;                       // 128 x 520  (133120 B)
    half  (*Ash)[520] = (half (*)[520])(sm + 133120);            // 32 x 520   (33280 B)
    float (*Gsh)[132] = (float(*)[132])(sm + 133120 + 33280);    // 32 x 132   (16896 B)

    const int bx    = blockIdx.x;
    const int text  = bx >> 6;
    const int chunk = (bx >> 4) & 3;
    const int slice = bx & 15;
    const int grp   = bx >> 4;           // 0..7
    const int tid   = threadIdx.x;
    const int w     = tid >> 5;
    const int wm    = (w & 1) * 16;      // warp M offset (0/16)
    const int nq    = w >> 1;            // gate index (0..3), 32 local cols

    // elementwise ownership: each thread owns row b, 4 consecutive cols j0..j0+3
    const int b  = tid >> 3;
    const int j0 = (tid & 7) * 4;
    float creg[4] = {0.f, 0.f, 0.f, 0.f};

    unsigned* const cnt = &g_cnt[grp][0];

    // load persistent W_hh slice: local row r -> global gate row (r>>5)*512 + slice*32 + (r&31)
#pragma unroll
    for (int v = 0; v < 32; v++) {
        int lin = v * 256 + tid;
        int r = lin >> 6, u = lin & 63;
        int grow = (r >> 5) * HDIM + slice * 32 + (r & 31);
        ((uint4*)&Wsh[r][0])[u] = ((const uint4*)&g_Whh[grow][0])[u];
    }
    // zero own h(0) slice in ping 0
    if (tid < 128) {
        int r = tid >> 2, u = tid & 3;
        ((uint2*)&g_h[0][text][chunk * 32 + r][slice * 32])[u] = make_uint2(0, 0);
    }
    __syncthreads();
    if (tid == 0) {
        unsigned one = 1u;
        asm volatile("red.release.gpu.global.add.u32 [%0], %1;" :: "l"(cnt), "r"(one) : "memory");
    }

    unsigned nbar = 1;
    int p = 0;

    for (int t = 0; t < SEQ; t++) {
        // ---- prefetch input-side gates (function of t only; in flight across the wait) ----
        const __half* xbase = &g_xg[text][t][chunk * 32 + b][slice * 32 + j0];
        uint2 xi2 = *(const uint2*)(xbase + 0 * HDIM);
        uint2 xf2 = *(const uint2*)(xbase + 1 * HDIM);
        uint2 xg2 = *(const uint2*)(xbase + 2 * HDIM);
        uint2 xo2 = *(const uint2*)(xbase + 3 * HDIM);

        // ---- barrier: wait until all 16 CTAs published h(t) ----
        if (tid == 0) {
            unsigned tgt = 16u * nbar;
            unsigned v;
            do {
                asm volatile("ld.acquire.gpu.global.u32 %0, [%1];" : "=r"(v) : "l"(cnt) : "memory");
            } while (v < tgt);
        }
        __syncthreads();

        // ---- issue cp.async of full h chunk [32 x 512] in 4 K-chunks of 128 cols ----
        const __half* hsrc = &g_h[p][text][chunk * 32][0];
#pragma unroll
        for (int c = 0; c < 4; c++) {
#pragma unroll
            for (int it = 0; it < 2; it++) {
                int lin = it * 256 + tid;          // 0..511
                int r = lin >> 4, u = lin & 15;
                uint32_t dst = smem_u32(&Ash[r][c * 128 + u * 8]);
                const __half* src = hsrc + (size_t)r * HDIM + c * 128 + u * 8;
                asm volatile("cp.async.cg.shared.global [%0], [%1], 16;" :: "r"(dst), "l"(src) : "memory");
            }
            asm volatile("cp.async.commit_group;" ::: "memory");
        }

        // ---- GEMM: gates[32 x 128] = h[32 x 512] @ Whh_slice^T, overlapped with cp.async ----
        wmma::fragment<wmma::accumulator, 16, 16, 16, float> accA[2], accB[2];
        wmma::fill_fragment(accA[0], 0.0f); wmma::fill_fragment(accA[1], 0.0f);
        wmma::fill_fragment(accB[0], 0.0f); wmma::fill_fragment(accB[1], 0.0f);

#define GEMM_CHUNK(CIDX, WG, ACC)                                                          \
        asm volatile("cp.async.wait_group %0;" :: "n"(WG) : "memory");                     \
        __syncthreads();                                                                   \
        _Pragma("unroll")                                                                  \
        for (int kk = (CIDX) * 8; kk < (CIDX) * 8 + 8; kk++) {                             \
            wmma::fragment<wmma::matrix_a, 16, 16, 16, half, wmma::row_major> af;          \
            wmma::load_matrix_sync(af, &Ash[wm][kk * 16], 520);                            \
            wmma::fragment<wmma::matrix_b, 16, 16, 16, half, wmma::col_major> bf;          \
            wmma::load_matrix_sync(bf, &Wsh[nq * 32][kk * 16], 520);                       \
            wmma::mma_sync(ACC[0], af, bf, ACC[0]);                                        \
            wmma::load_matrix_sync(bf, &Wsh[nq * 32 + 16][kk * 16], 520);                  \
            wmma::mma_sync(ACC[1], af, bf, ACC[1]);                                        \
        }

        GEMM_CHUNK(0, 3, accA)
        GEMM_CHUNK(1, 2, accB)
        GEMM_CHUNK(2, 1, accA)
        GEMM_CHUNK(3, 0, accB)
#undef GEMM_CHUNK

#pragma unroll
        for (int k = 0; k < 2; k++) {
#pragma unroll
            for (int i = 0; i < accA[k].num_elements; i++) accA[k].x[i] += accB[k].x[i];
        }
        wmma::store_matrix_sync(&Gsh[wm][nq * 32],      accA[0], 132, wmma::mem_row_major);
        wmma::store_matrix_sync(&Gsh[wm][nq * 32 + 16], accA[1], 132, wmma::mem_row_major);
        __syncthreads();

        // ---- gate nonlinearities + state update: 4 cells per thread (b, j0..j0+3) ----
        float4 iv4 = *(const float4*)&Gsh[b][j0];
        float4 fv4 = *(const float4*)&Gsh[b][32 + j0];
        float4 gv4 = *(const float4*)&Gsh[b][64 + j0];
        float4 ov4 = *(const float4*)&Gsh[b][96 + j0];
        float2 xil = __half22float2(*(const half2*)&xi2.x), xih = __half22float2(*(const half2*)&xi2.y);
        float2 xfl = __half22float2(*(const half2*)&xf2.x), xfh = __half22float2(*(const half2*)&xf2.y);
        float2 xgl = __half22float2(*(const half2*)&xg2.x), xgh = __half22float2(*(const half2*)&xg2.y);
        float2 xol = __half22float2(*(const half2*)&xo2.x), xoh = __half22float2(*(const half2*)&xo2.y);

        float iv[4] = {iv4.x + xil.x, iv4.y + xil.y, iv4.z + xih.x, iv4.w + xih.y};
        float fv[4] = {fv4.x + xfl.x, fv4.y + xfl.y, fv4.z + xfh.x, fv4.w + xfh.y};
        float gv[4] = {gv4.x + xgl.x, gv4.y + xgl.y, gv4.z + xgh.x, gv4.w + xgh.y};
        float ov[4] = {ov4.x + xol.x, ov4.y + xol.y, ov4.z + xoh.x, ov4.w + xoh.y};
        float hv[4];
#pragma unroll
        for (int e = 0; e < 4; e++) {
            float i_ = fast_sigmoid(iv[e]);
            float f_ = fast_sigmoid(fv[e]);
            float g_ = fast_tanh(gv[e]);
            float o_ = fast_sigmoid(ov[e]);
            float c  = f_ * creg[e] + i_ * g_;
            creg[e] = c;
            hv[e] = o_ * fast_tanh(c);
        }

        if (t < SEQ - 1) {
            // publish h(t+1) slice (8B store per thread)
            uint2 hp;
            ((half2*)&hp.x)[0] = __floats2half2_rn(hv[0], hv[1]);
            ((half2*)&hp.y)[0] = __floats2half2_rn(hv[2], hv[3]);
            *(uint2*)&g_h[p ^ 1][text][chunk * 32 + b][slice * 32 + j0] = hp;
            __syncthreads();          // all h stores issued before the release
            if (tid == 0) {
                unsigned one = 1u;
                asm volatile("red.release.gpu.global.add.u32 [%0], %1;" :: "l"(cnt), "r"(one) : "memory");
            }
            nbar++;
            p ^= 1;
        } else {
            float4 o4 = make_float4(hv[0], hv[1], hv[2], hv[3]);
            *(float4*)&out[((size_t)text * BATCH + chunk * 32 + b) * HDIM + slice * 32 + j0] = o4;
        }
    }
}

// ---------------- launch ----------------
extern "C" void kernel_launch(void* const* d_in, const int* in_sizes, int n_in,
                              void* d_out, int out_size) {
    (void)in_sizes; (void)n_in; (void)out_size;
    const float* x0  = (const float*)d_in[0];
    const float* x1  = (const float*)d_in[1];
    const float* Wih = (const float*)d_in[2];
    const float* Whh = (const float*)d_in[3];
    const float* bih = (const float*)d_in[4];
    const float* bhh = (const float*)d_in[5];
    float* out = (float*)d_out;

    const int REC_SMEM = 133120 + 33280 + 16896;   // 183296
    cudaFuncSetAttribute(xgemm_kernel,    cudaFuncAttributeMaxDynamicSharedMemorySize, 112640);
    cudaFuncSetAttribute(lstm_rec_kernel, cudaFuncAttributeMaxDynamicSharedMemorySize, REC_SMEM);

    prep_kernel<<<4096, 256>>>(Wih, Whh, bih, bhh);
    xgemm_kernel<<<dim3(8, 1024, 2), 256, 112640>>>(x0, x1);
    lstm_rec_kernel<<<128, 256, REC_SMEM>>>(out);
}

// round 9
// speedup vs baseline: 1.4248x; 1.0242x over previous
#include <cuda_runtime.h>
#include <cuda_fp16.h>
#include <cstdint>
#include <mma.h>

using namespace nvcuda;

#define BATCH 128
#define SEQ   512
#define IDIM  256
#define HDIM  512
#define GDIM  2048   // 4*H

// ---------------- device scratch (static: allocation-guard safe) ----------------
__device__ __half g_xg[2][SEQ][BATCH][GDIM];     // precomputed input-side gates, fp16 (512 MB)
__device__ __half g_h[2][2][BATCH][HDIM];        // ping-pong recurrent hidden state (fp16)
__device__ __half g_Wih[GDIM][IDIM];             // fp16 converted weights
__device__ __half g_Whh[GDIM][HDIM];
__device__ float  g_bias[GDIM];                  // b_ih + b_hh
__device__ unsigned g_cnt[8][32];                // per-group barrier counters, 1 per 128B sector

// ---------------- prep: fp32->fp16 weight convert, bias combine, counter reset ----------------
__global__ void prep_kernel(const float* __restrict__ Wih, const float* __restrict__ Whh,
                            const float* __restrict__ bih, const float* __restrict__ bhh) {
    int idx = blockIdx.x * blockDim.x + threadIdx.x;          // grid covers 1048576
    if (idx < GDIM * IDIM) (&g_Wih[0][0])[idx] = __float2half(Wih[idx]);
    if (idx < GDIM * HDIM) (&g_Whh[0][0])[idx] = __float2half(Whh[idx]);
    if (idx < GDIM)        g_bias[idx] = bih[idx] + bhh[idx];
    if (idx < 256)         (&g_cnt[0][0])[idx] = 0u;
}

// ---------------- input projection GEMM: xg[text][s][b][g] = x[b,s,:] @ W_ih[g,:] + bias[g] ----------------
__global__ void __launch_bounds__(256) xgemm_kernel(const float* __restrict__ x0,
                                                    const float* __restrict__ x1) {
    extern __shared__ char sm[];
    half  (*Xs)[72]  = (half (*)[72])sm;                            // 64 x 72 fp16
    half  (*Ws)[72]  = (half (*)[72])(sm + 64 * 72 * 2);            // 256 x 72 fp16
    float (*Os)[260] = (float(*)[260])(sm + 64 * 72 * 2 + 256 * 72 * 2); // 64 x 260 f32

    const int text = blockIdx.z;
    const float* __restrict__ x = text ? x1 : x0;
    const int n0 = blockIdx.x * 256;
    const int rt = blockIdx.y;
    const int s  = rt >> 1;
    const int b0 = (rt & 1) * 64;
    const int tid = threadIdx.x;
    const int w   = tid >> 5;
    const int wm  = (w & 1) * 32;
    const int wn  = (w >> 1) * 64;

    wmma::fragment<wmma::accumulator, 16, 16, 16, float> acc[2][4];
#pragma unroll
    for (int i = 0; i < 2; i++)
#pragma unroll
        for (int j = 0; j < 4; j++) wmma::fill_fragment(acc[i][j], 0.0f);

    for (int kc = 0; kc < IDIM; kc += 64) {
        {
            int r  = tid >> 2;
            int c0 = (tid & 3) * 16;
            const float4* src = (const float4*)(x + (size_t)(b0 + r) * (SEQ * IDIM) + (size_t)s * IDIM + kc + c0);
#pragma unroll
            for (int v = 0; v < 4; v++) {
                float4 f = src[v];
                half2* d = (half2*)&Xs[r][c0 + v * 4];
                d[0] = __floats2half2_rn(f.x, f.y);
                d[1] = __floats2half2_rn(f.z, f.w);
            }
        }
        {
            const uint4* src = (const uint4*)(&g_Wih[n0 + tid][kc]);
            uint4* dst = (uint4*)(&Ws[tid][0]);
#pragma unroll
            for (int v = 0; v < 8; v++) dst[v] = src[v];
        }
        __syncthreads();
#pragma unroll
        for (int kk = 0; kk < 4; kk++) {
            wmma::fragment<wmma::matrix_a, 16, 16, 16, half, wmma::row_major> af[2];
            wmma::load_matrix_sync(af[0], &Xs[wm][kk * 16], 72);
            wmma::load_matrix_sync(af[1], &Xs[wm + 16][kk * 16], 72);
#pragma unroll
            for (int nt = 0; nt < 4; nt++) {
                wmma::fragment<wmma::matrix_b, 16, 16, 16, half, wmma::col_major> bf;
                wmma::load_matrix_sync(bf, &Ws[wn + nt * 16][kk * 16], 72);
                wmma::mma_sync(acc[0][nt], af[0], bf, acc[0][nt]);
                wmma::mma_sync(acc[1][nt], af[1], bf, acc[1][nt]);
            }
        }
        __syncthreads();
    }
#pragma unroll
    for (int i = 0; i < 2; i++)
#pragma unroll
        for (int nt = 0; nt < 4; nt++)
            wmma::store_matrix_sync(&Os[wm + i * 16][wn + nt * 16], acc[i][nt], 260, wmma::mem_row_major);
    __syncthreads();

#pragma unroll
    for (int v = 0; v < 16; v++) {
        int lin = v * 256 + tid;
        int r = lin >> 6;
        int c = (lin & 63) * 4;
        int R = rt * 64 + r;                 // == s*128 + b
        half2 o0 = __floats2half2_rn(Os[r][c + 0] + g_bias[n0 + c + 0],
                                     Os[r][c + 1] + g_bias[n0 + c + 1]);
        half2 o1 = __floats2half2_rn(Os[r][c + 2] + g_bias[n0 + c + 2],
                                     Os[r][c + 3] + g_bias[n0 + c + 3]);
        half2* dst = (half2*)((&g_xg[0][0][0][0]) + ((size_t)text * 65536 + R) * GDIM + n0 + c);
        dst[0] = o0;
        dst[1] = o1;
    }
}

// ---------------- recurrence: 8 independent groups x 16 CTAs, L2 h exchange ----------------
__device__ __forceinline__ uint32_t smem_u32(const void* p) {
    uint32_t a;
    asm("{ .reg .u64 t; cvta.to.shared.u64 t, %1; cvt.u32.u64 %0, t; }" : "=r"(a) : "l"(p));
    return a;
}

__device__ __forceinline__ float fast_sigmoid(float x) {
    return __fdividef(1.0f, 1.0f + __expf(-x));          // MUFU.EX2 + MUFU.RCP path
}
__device__ __forceinline__ float fast_tanh(float x) {
    return 1.0f - __fdividef(2.0f, 1.0f + __expf(2.0f * x));
}

__global__ void __launch_bounds__(256) lstm_rec_kernel(float* __restrict__ out) {
    extern __shared__ char sm[];
    half  (*Wsh)[520] = (half (*)[520])sm;                       // 128 x 520  (133120 B)
    half  (*Ash)[520] = (half (*)[520])(sm + 133120);            // 32 x 520   (33280 B)
    float (*Gsh)[132] = (float(*)[132])(sm + 133120 + 33280);    // 32 x 132   (16896 B)

    const int bx    = blockIdx.x;
    const int text  = bx >> 6;
    const int chunk = (bx >> 4) & 3;
    const int slice = bx & 15;
    const int grp   = bx >> 4;           // 0..7
    const int tid   = threadIdx.x;
    const int w     = tid >> 5;
    const int wm    = (w & 1) * 16;      // warp M offset (0/16)
    const int nq    = w >> 1;            // gate index (0..3), 32 local cols

    // elementwise ownership: each thread owns row b, 4 consecutive cols j0..j0+3
    const int b  = tid >> 3;
    const int j0 = (tid & 7) * 4;
    float creg[4] = {0.f, 0.f, 0.f, 0.f};

    unsigned* const cnt = &g_cnt[grp][0];

    // load persistent W_hh slice: local row r -> global gate row (r>>5)*512 + slice*32 + (r&31)
#pragma unroll
    for (int v = 0; v < 32; v++) {
        int lin = v * 256 + tid;
        int r = lin >> 6, u = lin & 63;
        int grow = (r >> 5) * HDIM + slice * 32 + (r & 31);
        ((uint4*)&Wsh[r][0])[u] = ((const uint4*)&g_Whh[grow][0])[u];
    }
    // zero own h(0) slice in ping 0
    if (tid < 128) {
        int r = tid >> 2, u = tid & 3;
        ((uint2*)&g_h[0][text][chunk * 32 + r][slice * 32])[u] = make_uint2(0, 0);
    }
    __syncthreads();
    if (tid == 0) {
        unsigned one = 1u;
        asm volatile("red.release.gpu.global.add.u32 [%0], %1;" :: "l"(cnt), "r"(one) : "memory");
    }

    unsigned nbar = 1;
    int p = 0;

    for (int t = 0; t < SEQ; t++) {
        // ---- prefetch input-side gates (function of t only; in flight across the wait) ----
        const __half* xbase = &g_xg[text][t][chunk * 32 + b][slice * 32 + j0];
        uint2 xi2 = *(const uint2*)(xbase + 0 * HDIM);
        uint2 xf2 = *(const uint2*)(xbase + 1 * HDIM);
        uint2 xg2 = *(const uint2*)(xbase + 2 * HDIM);
        uint2 xo2 = *(const uint2*)(xbase + 3 * HDIM);

        // ---- per-warp barrier poll: all lanes spin on the counter (one coalesced L2 txn/warp).
        //      Each warp proceeds independently; cross-warp Ash ordering comes from the
        //      wait_group + syncthreads below.
        {
            unsigned tgt = 16u * nbar;
            unsigned v;
            do {
                asm volatile("ld.acquire.gpu.global.u32 %0, [%1];" : "=r"(v) : "l"(cnt) : "memory");
            } while (v < tgt);
        }

        // ---- issue cp.async of full h chunk [32 x 512] as two 16KB commit groups ----
        const __half* hsrc = &g_h[p][text][chunk * 32][0];
#pragma unroll
        for (int half_idx = 0; half_idx < 2; half_idx++) {
#pragma unroll
            for (int it = 0; it < 4; it++) {
                int lin = it * 256 + tid;                      // 0..1023 within this half
                int r = lin >> 5, u = lin & 31;                // row 0..31, 16B-chunk 0..31 (256 cols/half)
                uint32_t dst = smem_u32(&Ash[r][half_idx * 256 + u * 8]);
                const __half* src = hsrc + (size_t)r * HDIM + half_idx * 256 + u * 8;
                asm volatile("cp.async.cg.shared.global [%0], [%1], 16;" :: "r"(dst), "l"(src) : "memory");
            }
            asm volatile("cp.async.commit_group;" ::: "memory");
        }

        // ---- GEMM: gates[32 x 128] = h[32 x 512] @ Whh_slice^T, 2-phase overlap ----
        wmma::fragment<wmma::accumulator, 16, 16, 16, float> accA[2], accB[2];
        wmma::fill_fragment(accA[0], 0.0f); wmma::fill_fragment(accA[1], 0.0f);
        wmma::fill_fragment(accB[0], 0.0f); wmma::fill_fragment(accB[1], 0.0f);

#define GEMM_HALF(HIDX, WG, ACC0, ACC1)                                                    \
        asm volatile("cp.async.wait_group %0;" :: "n"(WG) : "memory");                     \
        __syncthreads();                                                                   \
        _Pragma("unroll")                                                                  \
        for (int kk = (HIDX) * 16; kk < (HIDX) * 16 + 16; kk += 2) {                       \
            wmma::fragment<wmma::matrix_a, 16, 16, 16, half, wmma::row_major> af0, af1;    \
            wmma::load_matrix_sync(af0, &Ash[wm][kk * 16], 520);                           \
            wmma::load_matrix_sync(af1, &Ash[wm][(kk + 1) * 16], 520);                     \
            wmma::fragment<wmma::matrix_b, 16, 16, 16, half, wmma::col_major> bf;          \
            wmma::load_matrix_sync(bf, &Wsh[nq * 32][kk * 16], 520);                       \
            wmma::mma_sync(ACC0[0], af0, bf, ACC0[0]);                                     \
            wmma::load_matrix_sync(bf, &Wsh[nq * 32 + 16][kk * 16], 520);                  \
            wmma::mma_sync(ACC0[1], af0, bf, ACC0[1]);                                     \
            wmma::load_matrix_sync(bf, &Wsh[nq * 32][(kk + 1) * 16], 520);                 \
            wmma::mma_sync(ACC1[0], af1, bf, ACC1[0]);                                     \
            wmma::load_matrix_sync(bf, &Wsh[nq * 32 + 16][(kk + 1) * 16], 520);            \
            wmma::mma_sync(ACC1[1], af1, bf, ACC1[1]);                                     \
        }

        GEMM_HALF(0, 1, accA, accB)
        GEMM_HALF(1, 0, accA, accB)
#undef GEMM_HALF

#pragma unroll
        for (int k = 0; k < 2; k++) {
#pragma unroll
            for (int i = 0; i < accA[k].num_elements; i++) accA[k].x[i] += accB[k].x[i];
        }
        wmma::store_matrix_sync(&Gsh[wm][nq * 32],      accA[0], 132, wmma::mem_row_major);
        wmma::store_matrix_sync(&Gsh[wm][nq * 32 + 16], accA[1], 132, wmma::mem_row_major);
        __syncthreads();

        // ---- gate nonlinearities + state update: 4 cells per thread (b, j0..j0+3) ----
        float4 iv4 = *(const float4*)&Gsh[b][j0];
        float4 fv4 = *(const float4*)&Gsh[b][32 + j0];
        float4 gv4 = *(const float4*)&Gsh[b][64 + j0];
        float4 ov4 = *(const float4*)&Gsh[b][96 + j0];
        float2 xil = __half22float2(*(const half2*)&xi2.x), xih = __half22float2(*(const half2*)&xi2.y);
        float2 xfl = __half22float2(*(const half2*)&xf2.x), xfh = __half22float2(*(const half2*)&xf2.y);
        float2 xgl = __half22float2(*(const half2*)&xg2.x), xgh = __half22float2(*(const half2*)&xg2.y);
        float2 xol = __half22float2(*(const half2*)&xo2.x), xoh = __half22float2(*(const half2*)&xo2.y);

        float iv[4] = {iv4.x + xil.x, iv4.y + xil.y, iv4.z + xih.x, iv4.w + xih.y};
        float fv[4] = {fv4.x + xfl.x, fv4.y + xfl.y, fv4.z + xfh.x, fv4.w + xfh.y};
        float gv[4] = {gv4.x + xgl.x, gv4.y + xgl.y, gv4.z + xgh.x, gv4.w + xgh.y};
        float ov[4] = {ov4.x + xol.x, ov4.y + xol.y, ov4.z + xoh.x, ov4.w + xoh.y};
        float hv[4];
#pragma unroll
        for (int e = 0; e < 4; e++) {
            float i_ = fast_sigmoid(iv[e]);
            float f_ = fast_sigmoid(fv[e]);
            float g_ = fast_tanh(gv[e]);
            float o_ = fast_sigmoid(ov[e]);
            float c  = f_ * creg[e] + i_ * g_;
            creg[e] = c;
            hv[e] = o_ * fast_tanh(c);
        }

        if (t < SEQ - 1) {
            // publish h(t+1) slice (8B store per thread)
            uint2 hp;
            ((half2*)&hp.x)[0] = __floats2half2_rn(hv[0], hv[1]);
            ((half2*)&hp.y)[0] = __floats2half2_rn(hv[2], hv[3]);
            *(uint2*)&g_h[p ^ 1][text][chunk * 32 + b][slice * 32 + j0] = hp;
            __syncthreads();          // all h stores issued before the release
            if (tid == 0) {
                unsigned one = 1u;
                asm volatile("red.release.gpu.global.add.u32 [%0], %1;" :: "l"(cnt), "r"(one) : "memory");
            }
            nbar++;
            p ^= 1;
        } else {
            float4 o4 = make_float4(hv[0], hv[1], hv[2], hv[3]);
            *(float4*)&out[((size_t)text * BATCH + chunk * 32 + b) * HDIM + slice * 32 + j0] = o4;
        }
    }
}

// ---------------- launch ----------------
extern "C" void kernel_launch(void* const* d_in, const int* in_sizes, int n_in,
                              void* d_out, int out_size) {
    (void)in_sizes; (void)n_in; (void)out_size;
    const float* x0  = (const float*)d_in[0];
    const float* x1  = (const float*)d_in[1];
    const float* Wih = (const float*)d_in[2];
    const float* Whh = (const float*)d_in[3];
    const float* bih = (const float*)d_in[4];
    const float* bhh = (const float*)d_in[5];
    float* out = (float*)d_out;

    const int REC_SMEM = 133120 + 33280 + 16896;   // 183296
    cudaFuncSetAttribute(xgemm_kernel,    cudaFuncAttributeMaxDynamicSharedMemorySize, 112640);
    cudaFuncSetAttribute(lstm_rec_kernel, cudaFuncAttributeMaxDynamicSharedMemorySize, REC_SMEM);

    prep_kernel<<<4096, 256>>>(Wih, Whh, bih, bhh);
    xgemm_kernel<<<dim3(8, 1024, 2), 256, 112640>>>(x0, x1);
    lstm_rec_kernel<<<128, 256, REC_SMEM>>>(out);
}

// round 10
// speedup vs baseline: 1.4390x; 1.0099x over previous
#include <cuda_runtime.h>
#include <cuda_fp16.h>
#include <cstdint>
#include <mma.h>

using namespace nvcuda;

#define BATCH 128
#define SEQ   512
#define IDIM  256
#define HDIM  512
#define GDIM  2048   // 4*H

// ---------------- device scratch (static: allocation-guard safe) ----------------
__device__ __half g_xg[2][SEQ][BATCH][GDIM];     // precomputed input-side gates, fp16 (512 MB)
__device__ __half g_h[2][2][BATCH][HDIM];        // ping-pong recurrent hidden state (fp16)
__device__ __half g_Wih[GDIM][IDIM];             // fp16 converted weights
__device__ __half g_Whh[GDIM][HDIM];
__device__ float  g_bias[GDIM];                  // b_ih + b_hh
__device__ unsigned g_cnt[8][32];                // per-group barrier counters, 1 per 128B sector

// ---------------- prep: fp32->fp16 weight convert, bias combine, counter reset ----------------
__global__ void prep_kernel(const float* __restrict__ Wih, const float* __restrict__ Whh,
                            const float* __restrict__ bih, const float* __restrict__ bhh) {
    int idx = blockIdx.x * blockDim.x + threadIdx.x;          // grid covers 1048576
    if (idx < GDIM * IDIM) (&g_Wih[0][0])[idx] = __float2half(Wih[idx]);
    if (idx < GDIM * HDIM) (&g_Whh[0][0])[idx] = __float2half(Whh[idx]);
    if (idx < GDIM)        g_bias[idx] = bih[idx] + bhh[idx];
    if (idx < 256)         (&g_cnt[0][0])[idx] = 0u;
}

// ---------------- input projection GEMM: xg[text][s][b][g] = x[b,s,:] @ W_ih[g,:] + bias[g] ----------------
__global__ void __launch_bounds__(256) xgemm_kernel(const float* __restrict__ x0,
                                                    const float* __restrict__ x1) {
    extern __shared__ char sm[];
    half  (*Xs)[72]  = (half (*)[72])sm;                            // 64 x 72 fp16
    half  (*Ws)[72]  = (half (*)[72])(sm + 64 * 72 * 2);            // 256 x 72 fp16
    float (*Os)[260] = (float(*)[260])(sm + 64 * 72 * 2 + 256 * 72 * 2); // 64 x 260 f32

    const int text = blockIdx.z;
    const float* __restrict__ x = text ? x1 : x0;
    const int n0 = blockIdx.x * 256;
    const int rt = blockIdx.y;
    const int s  = rt >> 1;
    const int b0 = (rt & 1) * 64;
    const int tid = threadIdx.x;
    const int w   = tid >> 5;
    const int wm  = (w & 1) * 32;
    const int wn  = (w >> 1) * 64;

    wmma::fragment<wmma::accumulator, 16, 16, 16, float> acc[2][4];
#pragma unroll
    for (int i = 0; i < 2; i++)
#pragma unroll
        for (int j = 0; j < 4; j++) wmma::fill_fragment(acc[i][j], 0.0f);

    for (int kc = 0; kc < IDIM; kc += 64) {
        {
            int r  = tid >> 2;
            int c0 = (tid & 3) * 16;
            const float4* src = (const float4*)(x + (size_t)(b0 + r) * (SEQ * IDIM) + (size_t)s * IDIM + kc + c0);
#pragma unroll
            for (int v = 0; v < 4; v++) {
                float4 f = src[v];
                half2* d = (half2*)&Xs[r][c0 + v * 4];
                d[0] = __floats2half2_rn(f.x, f.y);
                d[1] = __floats2half2_rn(f.z, f.w);
            }
        }
        {
            const uint4* src = (const uint4*)(&g_Wih[n0 + tid][kc]);
            uint4* dst = (uint4*)(&Ws[tid][0]);
#pragma unroll
            for (int v = 0; v < 8; v++) dst[v] = src[v];
        }
        __syncthreads();
#pragma unroll
        for (int kk = 0; kk < 4; kk++) {
            wmma::fragment<wmma::matrix_a, 16, 16, 16, half, wmma::row_major> af[2];
            wmma::load_matrix_sync(af[0], &Xs[wm][kk * 16], 72);
            wmma::load_matrix_sync(af[1], &Xs[wm + 16][kk * 16], 72);
#pragma unroll
            for (int nt = 0; nt < 4; nt++) {
                wmma::fragment<wmma::matrix_b, 16, 16, 16, half, wmma::col_major> bf;
                wmma::load_matrix_sync(bf, &Ws[wn + nt * 16][kk * 16], 72);
                wmma::mma_sync(acc[0][nt], af[0], bf, acc[0][nt]);
                wmma::mma_sync(acc[1][nt], af[1], bf, acc[1][nt]);
            }
        }
        __syncthreads();
    }
#pragma unroll
    for (int i = 0; i < 2; i++)
#pragma unroll
        for (int nt = 0; nt < 4; nt++)
            wmma::store_matrix_sync(&Os[wm + i * 16][wn + nt * 16], acc[i][nt], 260, wmma::mem_row_major);
    __syncthreads();

#pragma unroll
    for (int v = 0; v < 16; v++) {
        int lin = v * 256 + tid;
        int r = lin >> 6;
        int c = (lin & 63) * 4;
        int R = rt * 64 + r;                 // == s*128 + b
        half2 o0 = __floats2half2_rn(Os[r][c + 0] + g_bias[n0 + c + 0],
                                     Os[r][c + 1] + g_bias[n0 + c + 1]);
        half2 o1 = __floats2half2_rn(Os[r][c + 2] + g_bias[n0 + c + 2],
                                     Os[r][c + 3] + g_bias[n0 + c + 3]);
        half2* dst = (half2*)((&g_xg[0][0][0][0]) + ((size_t)text * 65536 + R) * GDIM + n0 + c);
        dst[0] = o0;
        dst[1] = o1;
    }
}

// ---------------- recurrence: 8 independent groups x 16 CTAs, L2 h exchange ----------------
__device__ __forceinline__ uint32_t smem_u32(const void* p) {
    uint32_t a;
    asm("{ .reg .u64 t; cvta.to.shared.u64 t, %1; cvt.u32.u64 %0, t; }" : "=r"(a) : "l"(p));
    return a;
}

__device__ __forceinline__ float fast_sigmoid(float x) {
    return __fdividef(1.0f, 1.0f + __expf(-x));          // MUFU.EX2 + MUFU.RCP path
}
__device__ __forceinline__ float fast_tanh(float x) {
    return 1.0f - __fdividef(2.0f, 1.0f + __expf(2.0f * x));
}

__global__ void __launch_bounds__(256) lstm_rec_kernel(float* __restrict__ out) {
    extern __shared__ char sm[];
    half  (*Wsh)[520] = (half (*)[520])sm;                       // 128 x 520  (133120 B)
    half  (*Ash)[520] = (half (*)[520])(sm + 133120);            // 32 x 520   (33280 B)
    float (*Gsh)[132] = (float(*)[132])(sm + 133120 + 33280);    // 32 x 132   (16896 B)

    const int bx    = blockIdx.x;
    const int text  = bx >> 6;
    const int chunk = (bx >> 4) & 3;
    const int slice = bx & 15;
    const int grp   = bx >> 4;           // 0..7
    const int tid   = threadIdx.x;
    const int w     = tid >> 5;
    const int wm    = (w & 1) * 16;      // warp M offset (0/16)
    const int nq    = w >> 1;            // gate index (0..3), 32 local cols

    // elementwise ownership: each thread owns row b, 4 consecutive cols j0..j0+3
    const int b  = tid >> 3;
    const int j0 = (tid & 7) * 4;
    float creg[4] = {0.f, 0.f, 0.f, 0.f};

    unsigned* const cnt = &g_cnt[grp][0];

    // load persistent W_hh slice: local row r -> global gate row (r>>5)*512 + slice*32 + (r&31)
#pragma unroll
    for (int v = 0; v < 32; v++) {
        int lin = v * 256 + tid;
        int r = lin >> 6, u = lin & 63;
        int grow = (r >> 5) * HDIM + slice * 32 + (r & 31);
        ((uint4*)&Wsh[r][0])[u] = ((const uint4*)&g_Whh[grow][0])[u];
    }
    // zero own h(0) slice in ping 0
    if (tid < 128) {
        int r = tid >> 2, u = tid & 3;
        ((uint2*)&g_h[0][text][chunk * 32 + r][slice * 32])[u] = make_uint2(0, 0);
    }
    __syncthreads();
    if (tid == 0) {
        unsigned one = 1u;
        asm volatile("red.release.gpu.global.add.u32 [%0], %1;" :: "l"(cnt), "r"(one) : "memory");
    }

    unsigned nbar = 1;
    int p = 0;

    for (int t = 0; t < SEQ; t++) {
        // ---- prefetch input-side gates (function of t only; in flight across the wait) ----
        const __half* xbase = &g_xg[text][t][chunk * 32 + b][slice * 32 + j0];
        uint2 xi2 = *(const uint2*)(xbase + 0 * HDIM);
        uint2 xf2 = *(const uint2*)(xbase + 1 * HDIM);
        uint2 xg2 = *(const uint2*)(xbase + 2 * HDIM);
        uint2 xo2 = *(const uint2*)(xbase + 3 * HDIM);

        // ---- per-warp barrier poll: all lanes spin on the counter (one coalesced L2 txn/warp).
        //      Each warp proceeds independently; cross-warp Ash ordering comes from the
        //      wait_group + syncthreads below.
        {
            unsigned tgt = 16u * nbar;
            unsigned v;
            do {
                asm volatile("ld.acquire.gpu.global.u32 %0, [%1];" : "=r"(v) : "l"(cnt) : "memory");
            } while (v < tgt);
        }

        // ---- issue cp.async of full h chunk [32 x 512] as two 16KB commit groups ----
        const __half* hsrc = &g_h[p][text][chunk * 32][0];
#pragma unroll
        for (int half_idx = 0; half_idx < 2; half_idx++) {
#pragma unroll
            for (int it = 0; it < 4; it++) {
                int lin = it * 256 + tid;                      // 0..1023 within this half
                int r = lin >> 5, u = lin & 31;                // row 0..31, 16B-chunk 0..31 (256 cols/half)
                uint32_t dst = smem_u32(&Ash[r][half_idx * 256 + u * 8]);
                const __half* src = hsrc + (size_t)r * HDIM + half_idx * 256 + u * 8;
                asm volatile("cp.async.cg.shared.global [%0], [%1], 16;" :: "r"(dst), "l"(src) : "memory");
            }
            asm volatile("cp.async.commit_group;" ::: "memory");
        }

        // ---- GEMM: gates[32 x 128] = h[32 x 512] @ Whh_slice^T, 2-phase overlap ----
        wmma::fragment<wmma::accumulator, 16, 16, 16, float> accA[2], accB[2];
        wmma::fill_fragment(accA[0], 0.0f); wmma::fill_fragment(accA[1], 0.0f);
        wmma::fill_fragment(accB[0], 0.0f); wmma::fill_fragment(accB[1], 0.0f);

#define GEMM_HALF(HIDX, WG, ACC0, ACC1)                                                    \
        asm volatile("cp.async.wait_group %0;" :: "n"(WG) : "memory");                     \
        __syncthreads();                                                                   \
        _Pragma("unroll")                                                                  \
        for (int kk = (HIDX) * 16; kk < (HIDX) * 16 + 16; kk += 2) {                       \
            wmma::fragment<wmma::matrix_a, 16, 16, 16, half, wmma::row_major> af0, af1;    \
            wmma::load_matrix_sync(af0, &Ash[wm][kk * 16], 520);                           \
            wmma::load_matrix_sync(af1, &Ash[wm][(kk + 1) * 16], 520);                     \
            wmma::fragment<wmma::matrix_b, 16, 16, 16, half, wmma::col_major> bf;          \
            wmma::load_matrix_sync(bf, &Wsh[nq * 32][kk * 16], 520);                       \
            wmma::mma_sync(ACC0[0], af0, bf, ACC0[0]);                                     \
            wmma::load_matrix_sync(bf, &Wsh[nq * 32 + 16][kk * 16], 520);                  \
            wmma::mma_sync(ACC0[1], af0, bf, ACC0[1]);                                     \
            wmma::load_matrix_sync(bf, &Wsh[nq * 32][(kk + 1) * 16], 520);                 \
            wmma::mma_sync(ACC1[0], af1, bf, ACC1[0]);                                     \
            wmma::load_matrix_sync(bf, &Wsh[nq * 32 + 16][(kk + 1) * 16], 520);            \
            wmma::mma_sync(ACC1[1], af1, bf, ACC1[1]);                                     \
        }

        GEMM_HALF(0, 1, accA, accB)
        GEMM_HALF(1, 0, accA, accB)
#undef GEMM_HALF

#pragma unroll
        for (int k = 0; k < 2; k++) {
#pragma unroll
            for (int i = 0; i < accA[k].num_elements; i++) accA[k].x[i] += accB[k].x[i];
        }
        wmma::store_matrix_sync(&Gsh[wm][nq * 32],      accA[0], 132, wmma::mem_row_major);
        wmma::store_matrix_sync(&Gsh[wm][nq * 32 + 16], accA[1], 132, wmma::mem_row_major);
        __syncthreads();

        // ---- gate nonlinearities + state update: 4 cells per thread (b, j0..j0+3) ----
        float4 iv4 = *(const float4*)&Gsh[b][j0];
        float4 fv4 = *(const float4*)&Gsh[b][32 + j0];
        float4 gv4 = *(const float4*)&Gsh[b][64 + j0];
        float4 ov4 = *(const float4*)&Gsh[b][96 + j0];
        float2 xil = __half22float2(*(const half2*)&xi2.x), xih = __half22float2(*(const half2*)&xi2.y);
        float2 xfl = __half22float2(*(const half2*)&xf2.x), xfh = __half22float2(*(const half2*)&xf2.y);
        float2 xgl = __half22float2(*(const half2*)&xg2.x), xgh = __half22float2(*(const half2*)&xg2.y);
        float2 xol = __half22float2(*(const half2*)&xo2.x), xoh = __half22float2(*(const half2*)&xo2.y);

        float iv[4] = {iv4.x + xil.x, iv4.y + xil.y, iv4.z + xih.x, iv4.w + xih.y};
        float fv[4] = {fv4.x + xfl.x, fv4.y + xfl.y, fv4.z + xfh.x, fv4.w + xfh.y};
        float gv[4] = {gv4.x + xgl.x, gv4.y + xgl.y, gv4.z + xgh.x, gv4.w + xgh.y};
        float ov[4] = {ov4.x + xol.x, ov4.y + xol.y, ov4.z + xoh.x, ov4.w + xoh.y};
        float hv[4];
#pragma unroll
        for (int e = 0; e < 4; e++) {
            float i_ = fast_sigmoid(iv[e]);
            float f_ = fast_sigmoid(fv[e]);
            float g_ = fast_tanh(gv[e]);
            float o_ = fast_sigmoid(ov[e]);
            float c  = f_ * creg[e] + i_ * g_;
            creg[e] = c;
            hv[e] = o_ * fast_tanh(c);
        }

        if (t < SEQ - 1) {
            // publish h(t+1) slice (8B store per thread)
            uint2 hp;
            ((half2*)&hp.x)[0] = __floats2half2_rn(hv[0], hv[1]);
            ((half2*)&hp.y)[0] = __floats2half2_rn(hv[2], hv[3]);
            *(uint2*)&g_h[p ^ 1][text][chunk * 32 + b][slice * 32 + j0] = hp;
            __syncthreads();          // all h stores issued before the release
            if (tid == 0) {
                unsigned one = 1u;
                asm volatile("red.release.gpu.global.add.u32 [%0], %1;" :: "l"(cnt), "r"(one) : "memory");
            }
            nbar++;
            p ^= 1;
        } else {
            float4 o4 = make_float4(hv[0], hv[1], hv[2], hv[3]);
            *(float4*)&out[((size_t)text * BATCH + chunk * 32 + b) * HDIM + slice * 32 + j0] = o4;
        }
    }
}

// ---------------- launch ----------------
extern "C" void kernel_launch(void* const* d_in, const int* in_sizes, int n_in,
                              void* d_out, int out_size) {
    (void)in_sizes; (void)n_in; (void)out_size;
    const float* x0  = (const float*)d_in[0];
    const float* x1  = (const float*)d_in[1];
    const float* Wih = (const float*)d_in[2];
    const float* Whh = (const float*)d_in[3];
    const float* bih = (const float*)d_in[4];
    const float* bhh = (const float*)d_in[5];
    float* out = (float*)d_out;

    const int REC_SMEM = 133120 + 33280 + 16896;   // 183296
    cudaFuncSetAttribute(xgemm_kernel,    cudaFuncAttributeMaxDynamicSharedMemorySize, 112640);
    cudaFuncSetAttribute(lstm_rec_kernel, cudaFuncAttributeMaxDynamicSharedMemorySize, REC_SMEM);

    prep_kernel<<<4096, 256>>>(Wih, Whh, bih, bhh);
    xgemm_kernel<<<dim3(8, 1024, 2), 256, 112640>>>(x0, x1);
    lstm_rec_kernel<<<128, 256, REC_SMEM>>>(out);
}

// round 11
// speedup vs baseline: 1.4394x; 1.0003x over previous
#include <cuda_runtime.h>
#include <cuda_fp16.h>
#include <cstdint>
#include <mma.h>

using namespace nvcuda;

#define BATCH 128
#define SEQ   512
#define IDIM  256
#define HDIM  512
#define GDIM  2048   // 4*H

// ---------------- device scratch (static: allocation-guard safe) ----------------
__device__ __half g_xg[2][SEQ][BATCH][GDIM];     // precomputed input-side gates, fp16 (512 MB)
__device__ __half g_h[2][2][BATCH][HDIM];        // ping-pong recurrent hidden state (fp16)
__device__ __half g_Wih[GDIM][IDIM];             // fp16 converted weights
__device__ __half g_Whh[GDIM][HDIM];
__device__ float  g_bias[GDIM];                  // b_ih + b_hh
__device__ unsigned g_cnt[8][32];                // per-group barrier counters, 1 per 128B sector

// ---------------- prep: fp32->fp16 weight convert, bias combine, counter reset ----------------
__global__ void prep_kernel(const float* __restrict__ Wih, const float* __restrict__ Whh,
                            const float* __restrict__ bih, const float* __restrict__ bhh) {
    int idx = blockIdx.x * blockDim.x + threadIdx.x;          // grid covers 1048576
    if (idx < GDIM * IDIM) (&g_Wih[0][0])[idx] = __float2half(Wih[idx]);
    if (idx < GDIM * HDIM) (&g_Whh[0][0])[idx] = __float2half(Whh[idx]);
    if (idx < GDIM)        g_bias[idx] = bih[idx] + bhh[idx];
    if (idx < 256)         (&g_cnt[0][0])[idx] = 0u;
}

// ---------------- input projection GEMM: xg[text][s][b][g] = x[b,s,:] @ W_ih[g,:] + bias[g] ----------------
__global__ void __launch_bounds__(256) xgemm_kernel(const float* __restrict__ x0,
                                                    const float* __restrict__ x1) {
    extern __shared__ char sm[];
    half  (*Xs)[72]  = (half (*)[72])sm;                            // 64 x 72 fp16
    half  (*Ws)[72]  = (half (*)[72])(sm + 64 * 72 * 2);            // 256 x 72 fp16
    float (*Os)[260] = (float(*)[260])(sm + 64 * 72 * 2 + 256 * 72 * 2); // 64 x 260 f32

    const int text = blockIdx.z;
    const float* __restrict__ x = text ? x1 : x0;
    const int n0 = blockIdx.x * 256;
    const int rt = blockIdx.y;
    const int s  = rt >> 1;
    const int b0 = (rt & 1) * 64;
    const int tid = threadIdx.x;
    const int w   = tid >> 5;
    const int wm  = (w & 1) * 32;
    const int wn  = (w >> 1) * 64;

    wmma::fragment<wmma::accumulator, 16, 16, 16, float> acc[2][4];
#pragma unroll
    for (int i = 0; i < 2; i++)
#pragma unroll
        for (int j = 0; j < 4; j++) wmma::fill_fragment(acc[i][j], 0.0f);

    for (int kc = 0; kc < IDIM; kc += 64) {
        {
            int r  = tid >> 2;
            int c0 = (tid & 3) * 16;
            const float4* src = (const float4*)(x + (size_t)(b0 + r) * (SEQ * IDIM) + (size_t)s * IDIM + kc + c0);
#pragma unroll
            for (int v = 0; v < 4; v++) {
                float4 f = src[v];
                half2* d = (half2*)&Xs[r][c0 + v * 4];
                d[0] = __floats2half2_rn(f.x, f.y);
                d[1] = __floats2half2_rn(f.z, f.w);
            }
        }
        {
            const uint4* src = (const uint4*)(&g_Wih[n0 + tid][kc]);
            uint4* dst = (uint4*)(&Ws[tid][0]);
#pragma unroll
            for (int v = 0; v < 8; v++) dst[v] = src[v];
        }
        __syncthreads();
#pragma unroll
        for (int kk = 0; kk < 4; kk++) {
            wmma::fragment<wmma::matrix_a, 16, 16, 16, half, wmma::row_major> af[2];
            wmma::load_matrix_sync(af[0], &Xs[wm][kk * 16], 72);
            wmma::load_matrix_sync(af[1], &Xs[wm + 16][kk * 16], 72);
#pragma unroll
            for (int nt = 0; nt < 4; nt++) {
                wmma::fragment<wmma::matrix_b, 16, 16, 16, half, wmma::col_major> bf;
                wmma::load_matrix_sync(bf, &Ws[wn + nt * 16][kk * 16], 72);
                wmma::mma_sync(acc[0][nt], af[0], bf, acc[0][nt]);
                wmma::mma_sync(acc[1][nt], af[1], bf, acc[1][nt]);
            }
        }
        __syncthreads();
    }
#pragma unroll
    for (int i = 0; i < 2; i++)
#pragma unroll
        for (int nt = 0; nt < 4; nt++)
            wmma::store_matrix_sync(&Os[wm + i * 16][wn + nt * 16], acc[i][nt], 260, wmma::mem_row_major);
    __syncthreads();

#pragma unroll
    for (int v = 0; v < 16; v++) {
        int lin = v * 256 + tid;
        int r = lin >> 6;
        int c = (lin & 63) * 4;
        int R = rt * 64 + r;                 // == s*128 + b
        half2 o0 = __floats2half2_rn(Os[r][c + 0] + g_bias[n0 + c + 0],
                                     Os[r][c + 1] + g_bias[n0 + c + 1]);
        half2 o1 = __floats2half2_rn(Os[r][c + 2] + g_bias[n0 + c + 2],
                                     Os[r][c + 3] + g_bias[n0 + c + 3]);
        half2* dst = (half2*)((&g_xg[0][0][0][0]) + ((size_t)text * 65536 + R) * GDIM + n0 + c);
        dst[0] = o0;
        dst[1] = o1;
    }
}

// ---------------- recurrence: 8 independent groups x 16 CTAs, L2 h exchange ----------------
__device__ __forceinline__ uint32_t smem_u32(const void* p) {
    uint32_t a;
    asm("{ .reg .u64 t; cvta.to.shared.u64 t, %1; cvt.u32.u64 %0, t; }" : "=r"(a) : "l"(p));
    return a;
}

__device__ __forceinline__ float fast_sigmoid(float x) {
    return __fdividef(1.0f, 1.0f + __expf(-x));          // MUFU.EX2 + MUFU.RCP path
}
__device__ __forceinline__ float fast_tanh(float x) {
    return 1.0f - __fdividef(2.0f, 1.0f + __expf(2.0f * x));
}

__global__ void __launch_bounds__(256) lstm_rec_kernel(float* __restrict__ out) {
    extern __shared__ char sm[];
    half  (*Wsh)[520] = (half (*)[520])sm;                       // 128 x 520  (133120 B)
    half  (*Ash)[520] = (half (*)[520])(sm + 133120);            // 32 x 520   (33280 B)
    float (*Gsh)[132] = (float(*)[132])(sm + 133120 + 33280);    // 32 x 132   (16896 B)

    const int bx    = blockIdx.x;
    const int text  = bx >> 6;
    const int chunk = (bx >> 4) & 3;
    const int slice = bx & 15;
    const int grp   = bx >> 4;           // 0..7
    const int tid   = threadIdx.x;
    const int w     = tid >> 5;
    const int wm    = (w & 1) * 16;      // warp M offset (0/16)
    const int nq    = w >> 1;            // gate index (0..3), 32 local cols

    // elementwise ownership: each thread owns row b, 4 consecutive cols j0..j0+3
    const int b  = tid >> 3;
    const int j0 = (tid & 7) * 4;
    float creg[4] = {0.f, 0.f, 0.f, 0.f};

    unsigned* const cnt = &g_cnt[grp][0];

    // load persistent W_hh slice: local row r -> global gate row (r>>5)*512 + slice*32 + (r&31)
#pragma unroll
    for (int v = 0; v < 32; v++) {
        int lin = v * 256 + tid;
        int r = lin >> 6, u = lin & 63;
        int grow = (r >> 5) * HDIM + slice * 32 + (r & 31);
        ((uint4*)&Wsh[r][0])[u] = ((const uint4*)&g_Whh[grow][0])[u];
    }
    // zero own h(0) slice in ping 0
    if (tid < 128) {
        int r = tid >> 2, u = tid & 3;
        ((uint2*)&g_h[0][text][chunk * 32 + r][slice * 32])[u] = make_uint2(0, 0);
    }
    __syncthreads();
    if (tid == 0) {
        unsigned one = 1u;
        asm volatile("red.release.gpu.global.add.u32 [%0], %1;" :: "l"(cnt), "r"(one) : "memory");
    }

    unsigned nbar = 1;
    int p = 0;

    for (int t = 0; t < SEQ; t++) {
        // ---- prefetch input-side gates (function of t only; in flight across the wait) ----
        const __half* xbase = &g_xg[text][t][chunk * 32 + b][slice * 32 + j0];
        uint2 xi2 = *(const uint2*)(xbase + 0 * HDIM);
        uint2 xf2 = *(const uint2*)(xbase + 1 * HDIM);
        uint2 xg2 = *(const uint2*)(xbase + 2 * HDIM);
        uint2 xo2 = *(const uint2*)(xbase + 3 * HDIM);

        // ---- per-warp barrier poll: all lanes spin on the counter (one coalesced L2 txn/warp).
        //      Each warp proceeds independently; cross-warp Ash ordering comes from the
        //      wait_group + syncthreads below.
        {
            unsigned tgt = 16u * nbar;
            unsigned v;
            do {
                asm volatile("ld.acquire.gpu.global.u32 %0, [%1];" : "=r"(v) : "l"(cnt) : "memory");
            } while (v < tgt);
        }

        // ---- issue cp.async of full h chunk [32 x 512] as two 16KB commit groups ----
        const __half* hsrc = &g_h[p][text][chunk * 32][0];
#pragma unroll
        for (int half_idx = 0; half_idx < 2; half_idx++) {
#pragma unroll
            for (int it = 0; it < 4; it++) {
                int lin = it * 256 + tid;                      // 0..1023 within this half
                int r = lin >> 5, u = lin & 31;                // row 0..31, 16B-chunk 0..31 (256 cols/half)
                uint32_t dst = smem_u32(&Ash[r][half_idx * 256 + u * 8]);
                const __half* src = hsrc + (size_t)r * HDIM + half_idx * 256 + u * 8;
                asm volatile("cp.async.cg.shared.global [%0], [%1], 16;" :: "r"(dst), "l"(src) : "memory");
            }
            asm volatile("cp.async.commit_group;" ::: "memory");
        }

        // ---- GEMM: gates[32 x 128] = h[32 x 512] @ Whh_slice^T, 2-phase overlap ----
        wmma::fragment<wmma::accumulator, 16, 16, 16, float> accA[2], accB[2];
        wmma::fill_fragment(accA[0], 0.0f); wmma::fill_fragment(accA[1], 0.0f);
        wmma::fill_fragment(accB[0], 0.0f); wmma::fill_fragment(accB[1], 0.0f);

#define GEMM_HALF(HIDX, WG, ACC0, ACC1)                                                    \
        asm volatile("cp.async.wait_group %0;" :: "n"(WG) : "memory");                     \
        __syncthreads();                                                                   \
        _Pragma("unroll")                                                                  \
        for (int kk = (HIDX) * 16; kk < (HIDX) * 16 + 16; kk += 2) {                       \
            wmma::fragment<wmma::matrix_a, 16, 16, 16, half, wmma::row_major> af0, af1;    \
            wmma::load_matrix_sync(af0, &Ash[wm][kk * 16], 520);                           \
            wmma::load_matrix_sync(af1, &Ash[wm][(kk + 1) * 16], 520);                     \
            wmma::fragment<wmma::matrix_b, 16, 16, 16, half, wmma::col_major> bf;          \
            wmma::load_matrix_sync(bf, &Wsh[nq * 32][kk * 16], 520);                       \
            wmma::mma_sync(ACC0[0], af0, bf, ACC0[0]);                                     \
            wmma::load_matrix_sync(bf, &Wsh[nq * 32 + 16][kk * 16], 520);                  \
            wmma::mma_sync(ACC0[1], af0, bf, ACC0[1]);                                     \
            wmma::load_matrix_sync(bf, &Wsh[nq * 32][(kk + 1) * 16], 520);                 \
            wmma::mma_sync(ACC1[0], af1, bf, ACC1[0]);                                     \
            wmma::load_matrix_sync(bf, &Wsh[nq * 32 + 16][(kk + 1) * 16], 520);            \
            wmma::mma_sync(ACC1[1], af1, bf, ACC1[1]);                                     \
        }

        GEMM_HALF(0, 1, accA, accB)
        GEMM_HALF(1, 0, accA, accB)
#undef GEMM_HALF

#pragma unroll
        for (int k = 0; k < 2; k++) {
#pragma unroll
            for (int i = 0; i < accA[k].num_elements; i++) accA[k].x[i] += accB[k].x[i];
        }
        wmma::store_matrix_sync(&Gsh[wm][nq * 32],      accA[0], 132, wmma::mem_row_major);
        wmma::store_matrix_sync(&Gsh[wm][nq * 32 + 16], accA[1], 132, wmma::mem_row_major);
        __syncthreads();

        // ---- gate nonlinearities + state update: 4 cells per thread (b, j0..j0+3) ----
        float4 iv4 = *(const float4*)&Gsh[b][j0];
        float4 fv4 = *(const float4*)&Gsh[b][32 + j0];
        float4 gv4 = *(const float4*)&Gsh[b][64 + j0];
        float4 ov4 = *(const float4*)&Gsh[b][96 + j0];
        float2 xil = __half22float2(*(const half2*)&xi2.x), xih = __half22float2(*(const half2*)&xi2.y);
        float2 xfl = __half22float2(*(const half2*)&xf2.x), xfh = __half22float2(*(const half2*)&xf2.y);
        float2 xgl = __half22float2(*(const half2*)&xg2.x), xgh = __half22float2(*(const half2*)&xg2.y);
        float2 xol = __half22float2(*(const half2*)&xo2.x), xoh = __half22float2(*(const half2*)&xo2.y);

        float iv[4] = {iv4.x + xil.x, iv4.y + xil.y, iv4.z + xih.x, iv4.w + xih.y};
        float fv[4] = {fv4.x + xfl.x, fv4.y + xfl.y, fv4.z + xfh.x, fv4.w + xfh.y};
        float gv[4] = {gv4.x + xgl.x, gv4.y + xgl.y, gv4.z + xgh.x, gv4.w + xgh.y};
        float ov[4] = {ov4.x + xol.x, ov4.y + xol.y, ov4.z + xoh.x, ov4.w + xoh.y};
        float hv[4];
#pragma unroll
        for (int e = 0; e < 4; e++) {
            float i_ = fast_sigmoid(iv[e]);
            float f_ = fast_sigmoid(fv[e]);
            float g_ = fast_tanh(gv[e]);
            float o_ = fast_sigmoid(ov[e]);
            float c  = f_ * creg[e] + i_ * g_;
            creg[e] = c;
            hv[e] = o_ * fast_tanh(c);
        }

        if (t < SEQ - 1) {
            // publish h(t+1) slice (8B store per thread)
            uint2 hp;
            ((half2*)&hp.x)[0] = __floats2half2_rn(hv[0], hv[1]);
            ((half2*)&hp.y)[0] = __floats2half2_rn(hv[2], hv[3]);
            *(uint2*)&g_h[p ^ 1][text][chunk * 32 + b][slice * 32 + j0] = hp;
            __syncthreads();          // all h stores issued before the release
            if (tid == 0) {
                unsigned one = 1u;
                asm volatile("red.release.gpu.global.add.u32 [%0], %1;" :: "l"(cnt), "r"(one) : "memory");
            }
            nbar++;
            p ^= 1;
        } else {
            float4 o4 = make_float4(hv[0], hv[1], hv[2], hv[3]);
            *(float4*)&out[((size_t)text * BATCH + chunk * 32 + b) * HDIM + slice * 32 + j0] = o4;
        }
    }
}

// ---------------- launch ----------------
extern "C" void kernel_launch(void* const* d_in, const int* in_sizes, int n_in,
                              void* d_out, int out_size) {
    (void)in_sizes; (void)n_in; (void)out_size;
    const float* x0  = (const float*)d_in[0];
    const float* x1  = (const float*)d_in[1];
    const float* Wih = (const float*)d_in[2];
    const float* Whh = (const float*)d_in[3];
    const float* bih = (const float*)d_in[4];
    const float* bhh = (const float*)d_in[5];
    float* out = (float*)d_out;

    const int REC_SMEM = 133120 + 33280 + 16896;   // 183296
    cudaFuncSetAttribute(xgemm_kernel,    cudaFuncAttributeMaxDynamicSharedMemorySize, 112640);
    cudaFuncSetAttribute(lstm_rec_kernel, cudaFuncAttributeMaxDynamicSharedMemorySize, REC_SMEM);

    prep_kernel<<<4096, 256>>>(Wih, Whh, bih, bhh);
    xgemm_kernel<<<dim3(8, 1024, 2), 256, 112640>>>(x0, x1);
    lstm_rec_kernel<<<128, 256, REC_SMEM>>>(out);
}

// round 12
// speedup vs baseline: 1.4395x; 1.0000x over previous
#include <cuda_runtime.h>
#include <cuda_fp16.h>
#include <cstdint>
#include <mma.h>

using namespace nvcuda;

#define BATCH 128
#define SEQ   512
#define IDIM  256
#define HDIM  512
#define GDIM  2048   // 4*H

// ---------------- device scratch (static: allocation-guard safe) ----------------
__device__ __half g_xg[2][SEQ][BATCH][GDIM];     // precomputed input-side gates, fp16 (512 MB)
__device__ __half g_h[2][2][BATCH][HDIM];        // ping-pong recurrent hidden state (fp16)
__device__ __half g_Wih[GDIM][IDIM];             // fp16 converted weights
__device__ __half g_Whh[GDIM][HDIM];
__device__ float  g_bias[GDIM];                  // b_ih + b_hh
__device__ unsigned g_cnt[8][32];                // per-group barrier counters, 1 per 128B sector

// ---------------- prep: fp32->fp16 weight convert, bias combine, counter reset ----------------
__global__ void prep_kernel(const float* __restrict__ Wih, const float* __restrict__ Whh,
                            const float* __restrict__ bih, const float* __restrict__ bhh) {
    int idx = blockIdx.x * blockDim.x + threadIdx.x;          // grid covers 1048576
    if (idx < GDIM * IDIM) (&g_Wih[0][0])[idx] = __float2half(Wih[idx]);
    if (idx < GDIM * HDIM) (&g_Whh[0][0])[idx] = __float2half(Whh[idx]);
    if (idx < GDIM)        g_bias[idx] = bih[idx] + bhh[idx];
    if (idx < 256)         (&g_cnt[0][0])[idx] = 0u;
}

// ---------------- input projection GEMM: xg[text][s][b][g] = x[b,s,:] @ W_ih[g,:] + bias[g] ----------------
__global__ void __launch_bounds__(256) xgemm_kernel(const float* __restrict__ x0,
                                                    const float* __restrict__ x1) {
    extern __shared__ char sm[];
    half  (*Xs)[72]  = (half (*)[72])sm;                            // 64 x 72 fp16
    half  (*Ws)[72]  = (half (*)[72])(sm + 64 * 72 * 2);            // 256 x 72 fp16
    float (*Os)[260] = (float(*)[260])(sm + 64 * 72 * 2 + 256 * 72 * 2); // 64 x 260 f32

    const int text = blockIdx.z;
    const float* __restrict__ x = text ? x1 : x0;
    const int n0 = blockIdx.x * 256;
    const int rt = blockIdx.y;
    const int s  = rt >> 1;
    const int b0 = (rt & 1) * 64;
    const int tid = threadIdx.x;
    const int w   = tid >> 5;
    const int wm  = (w & 1) * 32;
    const int wn  = (w >> 1) * 64;

    wmma::fragment<wmma::accumulator, 16, 16, 16, float> acc[2][4];
#pragma unroll
    for (int i = 0; i < 2; i++)
#pragma unroll
        for (int j = 0; j < 4; j++) wmma::fill_fragment(acc[i][j], 0.0f);

    for (int kc = 0; kc < IDIM; kc += 64) {
        {
            int r  = tid >> 2;
            int c0 = (tid & 3) * 16;
            const float4* src = (const float4*)(x + (size_t)(b0 + r) * (SEQ * IDIM) + (size_t)s * IDIM + kc + c0);
#pragma unroll
            for (int v = 0; v < 4; v++) {
                float4 f = src[v];
                half2* d = (half2*)&Xs[r][c0 + v * 4];
                d[0] = __floats2half2_rn(f.x, f.y);
                d[1] = __floats2half2_rn(f.z, f.w);
            }
        }
        {
            const uint4* src = (const uint4*)(&g_Wih[n0 + tid][kc]);
            uint4* dst = (uint4*)(&Ws[tid][0]);
#pragma unroll
            for (int v = 0; v < 8; v++) dst[v] = src[v];
        }
        __syncthreads();
#pragma unroll
        for (int kk = 0; kk < 4; kk++) {
            wmma::fragment<wmma::matrix_a, 16, 16, 16, half, wmma::row_major> af[2];
            wmma::load_matrix_sync(af[0], &Xs[wm][kk * 16], 72);
            wmma::load_matrix_sync(af[1], &Xs[wm + 16][kk * 16], 72);
#pragma unroll
            for (int nt = 0; nt < 4; nt++) {
                wmma::fragment<wmma::matrix_b, 16, 16, 16, half, wmma::col_major> bf;
                wmma::load_matrix_sync(bf, &Ws[wn + nt * 16][kk * 16], 72);
                wmma::mma_sync(acc[0][nt], af[0], bf, acc[0][nt]);
                wmma::mma_sync(acc[1][nt], af[1], bf, acc[1][nt]);
            }
        }
        __syncthreads();
    }
#pragma unroll
    for (int i = 0; i < 2; i++)
#pragma unroll
        for (int nt = 0; nt < 4; nt++)
            wmma::store_matrix_sync(&Os[wm + i * 16][wn + nt * 16], acc[i][nt], 260, wmma::mem_row_major);
    __syncthreads();

#pragma unroll
    for (int v = 0; v < 16; v++) {
        int lin = v * 256 + tid;
        int r = lin >> 6;
        int c = (lin & 63) * 4;
        int R = rt * 64 + r;                 // == s*128 + b
        half2 o0 = __floats2half2_rn(Os[r][c + 0] + g_bias[n0 + c + 0],
                                     Os[r][c + 1] + g_bias[n0 + c + 1]);
        half2 o1 = __floats2half2_rn(Os[r][c + 2] + g_bias[n0 + c + 2],
                                     Os[r][c + 3] + g_bias[n0 + c + 3]);
        half2* dst = (half2*)((&g_xg[0][0][0][0]) + ((size_t)text * 65536 + R) * GDIM + n0 + c);
        dst[0] = o0;
        dst[1] = o1;
    }
}

// ---------------- recurrence: 8 independent groups x 16 CTAs, L2 h exchange ----------------
__device__ __forceinline__ uint32_t smem_u32(const void* p) {
    uint32_t a;
    asm("{ .reg .u64 t; cvta.to.shared.u64 t, %1; cvt.u32.u64 %0, t; }" : "=r"(a) : "l"(p));
    return a;
}

__device__ __forceinline__ float fast_sigmoid(float x) {
    return __fdividef(1.0f, 1.0f + __expf(-x));          // MUFU.EX2 + MUFU.RCP path
}
__device__ __forceinline__ float fast_tanh(float x) {
    return 1.0f - __fdividef(2.0f, 1.0f + __expf(2.0f * x));
}

__global__ void __launch_bounds__(256) lstm_rec_kernel(float* __restrict__ out) {
    extern __shared__ char sm[];
    half  (*Wsh)[520] = (half (*)[520])sm;                       // 128 x 520  (133120 B)
    half  (*Ash)[520] = (half (*)[520])(sm + 133120);            // 32 x 520   (33280 B)
    float (*Gsh)[132] = (float(*)[132])(sm + 133120 + 33280);    // 32 x 132   (16896 B)

    const int bx    = blockIdx.x;
    const int text  = bx >> 6;
    const int chunk = (bx >> 4) & 3;
    const int slice = bx & 15;
    const int grp   = bx >> 4;           // 0..7
    const int tid   = threadIdx.x;
    const int w     = tid >> 5;
    const int wm    = (w & 1) * 16;      // warp M offset (0/16)
    const int nq    = w >> 1;            // gate index (0..3), 32 local cols

    // elementwise ownership: each thread owns row b, 4 consecutive cols j0..j0+3
    const int b  = tid >> 3;
    const int j0 = (tid & 7) * 4;
    float creg[4] = {0.f, 0.f, 0.f, 0.f};

    unsigned* const cnt = &g_cnt[grp][0];

    // load persistent W_hh slice: local row r -> global gate row (r>>5)*512 + slice*32 + (r&31)
#pragma unroll
    for (int v = 0; v < 32; v++) {
        int lin = v * 256 + tid;
        int r = lin >> 6, u = lin & 63;
        int grow = (r >> 5) * HDIM + slice * 32 + (r & 31);
        ((uint4*)&Wsh[r][0])[u] = ((const uint4*)&g_Whh[grow][0])[u];
    }
    // zero own h(0) slice in ping 0
    if (tid < 128) {
        int r = tid >> 2, u = tid & 3;
        ((uint2*)&g_h[0][text][chunk * 32 + r][slice * 32])[u] = make_uint2(0, 0);
    }
    __syncthreads();
    if (tid == 0) {
        unsigned one = 1u;
        asm volatile("red.release.gpu.global.add.u32 [%0], %1;" :: "l"(cnt), "r"(one) : "memory");
    }

    unsigned nbar = 1;
    int p = 0;

    for (int t = 0; t < SEQ; t++) {
        // ---- prefetch input-side gates (function of t only; in flight across the wait) ----
        const __half* xbase = &g_xg[text][t][chunk * 32 + b][slice * 32 + j0];
        uint2 xi2 = *(const uint2*)(xbase + 0 * HDIM);
        uint2 xf2 = *(const uint2*)(xbase + 1 * HDIM);
        uint2 xg2 = *(const uint2*)(xbase + 2 * HDIM);
        uint2 xo2 = *(const uint2*)(xbase + 3 * HDIM);

        // ---- per-warp barrier poll: all lanes spin on the counter (one coalesced L2 txn/warp).
        //      Each warp proceeds independently; cross-warp Ash ordering comes from the
        //      wait_group + syncthreads below.
        {
            unsigned tgt = 16u * nbar;
            unsigned v;
            do {
                asm volatile("ld.acquire.gpu.global.u32 %0, [%1];" : "=r"(v) : "l"(cnt) : "memory");
            } while (v < tgt);
        }

        // ---- issue cp.async of full h chunk [32 x 512] as two 16KB commit groups ----
        const __half* hsrc = &g_h[p][text][chunk * 32][0];
#pragma unroll
        for (int half_idx = 0; half_idx < 2; half_idx++) {
#pragma unroll
            for (int it = 0; it < 4; it++) {
                int lin = it * 256 + tid;                      // 0..1023 within this half
                int r = lin >> 5, u = lin & 31;                // row 0..31, 16B-chunk 0..31 (256 cols/half)
                uint32_t dst = smem_u32(&Ash[r][half_idx * 256 + u * 8]);
                const __half* src = hsrc + (size_t)r * HDIM + half_idx * 256 + u * 8;
                asm volatile("cp.async.cg.shared.global [%0], [%1], 16;" :: "r"(dst), "l"(src) : "memory");
            }
            asm volatile("cp.async.commit_group;" ::: "memory");
        }

        // ---- GEMM: gates[32 x 128] = h[32 x 512] @ Whh_slice^T, 2-phase overlap ----
        wmma::fragment<wmma::accumulator, 16, 16, 16, float> accA[2], accB[2];
        wmma::fill_fragment(accA[0], 0.0f); wmma::fill_fragment(accA[1], 0.0f);
        wmma::fill_fragment(accB[0], 0.0f); wmma::fill_fragment(accB[1], 0.0f);

#define GEMM_HALF(HIDX, WG, ACC0, ACC1)                                                    \
        asm volatile("cp.async.wait_group %0;" :: "n"(WG) : "memory");                     \
        __syncthreads();                                                                   \
        _Pragma("unroll")                                                                  \
        for (int kk = (HIDX) * 16; kk < (HIDX) * 16 + 16; kk += 2) {                       \
            wmma::fragment<wmma::matrix_a, 16, 16, 16, half, wmma::row_major> af0, af1;    \
            wmma::load_matrix_sync(af0, &Ash[wm][kk * 16], 520);                           \
            wmma::load_matrix_sync(af1, &Ash[wm][(kk + 1) * 16], 520);                     \
            wmma::fragment<wmma::matrix_b, 16, 16, 16, half, wmma::col_major> bf;          \
            wmma::load_matrix_sync(bf, &Wsh[nq * 32][kk * 16], 520);                       \
            wmma::mma_sync(ACC0[0], af0, bf, ACC0[0]);                                     \
            wmma::load_matrix_sync(bf, &Wsh[nq * 32 + 16][kk * 16], 520);                  \
            wmma::mma_sync(ACC0[1], af0, bf, ACC0[1]);                                     \
            wmma::load_matrix_sync(bf, &Wsh[nq * 32][(kk + 1) * 16], 520);                 \
            wmma::mma_sync(ACC1[0], af1, bf, ACC1[0]);                                     \
            wmma::load_matrix_sync(bf, &Wsh[nq * 32 + 16][(kk + 1) * 16], 520);            \
            wmma::mma_sync(ACC1[1], af1, bf, ACC1[1]);                                     \
        }

        GEMM_HALF(0, 1, accA, accB)
        GEMM_HALF(1, 0, accA, accB)
#undef GEMM_HALF

#pragma unroll
        for (int k = 0; k < 2; k++) {
#pragma unroll
            for (int i = 0; i < accA[k].num_elements; i++) accA[k].x[i] += accB[k].x[i];
        }
        wmma::store_matrix_sync(&Gsh[wm][nq * 32],      accA[0], 132, wmma::mem_row_major);
        wmma::store_matrix_sync(&Gsh[wm][nq * 32 + 16], accA[1], 132, wmma::mem_row_major);
        __syncthreads();

        // ---- gate nonlinearities + state update: 4 cells per thread (b, j0..j0+3) ----
        float4 iv4 = *(const float4*)&Gsh[b][j0];
        float4 fv4 = *(const float4*)&Gsh[b][32 + j0];
        float4 gv4 = *(const float4*)&Gsh[b][64 + j0];
        float4 ov4 = *(const float4*)&Gsh[b][96 + j0];
        float2 xil = __half22float2(*(const half2*)&xi2.x), xih = __half22float2(*(const half2*)&xi2.y);
        float2 xfl = __half22float2(*(const half2*)&xf2.x), xfh = __half22float2(*(const half2*)&xf2.y);
        float2 xgl = __half22float2(*(const half2*)&xg2.x), xgh = __half22float2(*(const half2*)&xg2.y);
        float2 xol = __half22float2(*(const half2*)&xo2.x), xoh = __half22float2(*(const half2*)&xo2.y);

        float iv[4] = {iv4.x + xil.x, iv4.y + xil.y, iv4.z + xih.x, iv4.w + xih.y};
        float fv[4] = {fv4.x + xfl.x, fv4.y + xfl.y, fv4.z + xfh.x, fv4.w + xfh.y};
        float gv[4] = {gv4.x + xgl.x, gv4.y + xgl.y, gv4.z + xgh.x, gv4.w + xgh.y};
        float ov[4] = {ov4.x + xol.x, ov4.y + xol.y, ov4.z + xoh.x, ov4.w + xoh.y};
        float hv[4];
#pragma unroll
        for (int e = 0; e < 4; e++) {
            float i_ = fast_sigmoid(iv[e]);
            float f_ = fast_sigmoid(fv[e]);
            float g_ = fast_tanh(gv[e]);
            float o_ = fast_sigmoid(ov[e]);
            float c  = f_ * creg[e] + i_ * g_;
            creg[e] = c;
            hv[e] = o_ * fast_tanh(c);
        }

        if (t < SEQ - 1) {
            // publish h(t+1) slice (8B store per thread)
            uint2 hp;
            ((half2*)&hp.x)[0] = __floats2half2_rn(hv[0], hv[1]);
            ((half2*)&hp.y)[0] = __floats2half2_rn(hv[2], hv[3]);
            *(uint2*)&g_h[p ^ 1][text][chunk * 32 + b][slice * 32 + j0] = hp;
            __syncthreads();          // all h stores issued before the release
            if (tid == 0) {
                unsigned one = 1u;
                asm volatile("red.release.gpu.global.add.u32 [%0], %1;" :: "l"(cnt), "r"(one) : "memory");
            }
            nbar++;
            p ^= 1;
        } else {
            float4 o4 = make_float4(hv[0], hv[1], hv[2], hv[3]);
            *(float4*)&out[((size_t)text * BATCH + chunk * 32 + b) * HDIM + slice * 32 + j0] = o4;
        }
    }
}

// ---------------- launch ----------------
extern "C" void kernel_launch(void* const* d_in, const int* in_sizes, int n_in,
                              void* d_out, int out_size) {
    (void)in_sizes; (void)n_in; (void)out_size;
    const float* x0  = (const float*)d_in[0];
    const float* x1  = (const float*)d_in[1];
    const float* Wih = (const float*)d_in[2];
    const float* Whh = (const float*)d_in[3];
    const float* bih = (const float*)d_in[4];
    const float* bhh = (const float*)d_in[5];
    float* out = (float*)d_out;

    const int REC_SMEM = 133120 + 33280 + 16896;   // 183296
    cudaFuncSetAttribute(xgemm_kernel,    cudaFuncAttributeMaxDynamicSharedMemorySize, 112640);
    cudaFuncSetAttribute(lstm_rec_kernel, cudaFuncAttributeMaxDynamicSharedMemorySize, REC_SMEM);

    prep_kernel<<<4096, 256>>>(Wih, Whh, bih, bhh);
    xgemm_kernel<<<dim3(8, 1024, 2), 256, 112640>>>(x0, x1);
    lstm_rec_kernel<<<128, 256, REC_SMEM>>>(out);
}

// round 13
// speedup vs baseline: 1.4419x; 1.0017x over previous
#include <cuda_runtime.h>
#include <cuda_fp16.h>
#include <cstdint>
#include <mma.h>

using namespace nvcuda;

#define BATCH 128
#define SEQ   512
#define IDIM  256
#define HDIM  512
#define GDIM  2048   // 4*H

// ---------------- device scratch (static: allocation-guard safe) ----------------
__device__ __half g_xg[2][SEQ][BATCH][GDIM];     // precomputed input-side gates, fp16 (512 MB)
__device__ __half g_h[2][2][BATCH][HDIM];        // ping-pong recurrent hidden state (fp16)
__device__ __half g_Wih[GDIM][IDIM];             // fp16 converted weights
__device__ __half g_Whh[GDIM][HDIM];
__device__ float  g_bias[GDIM];                  // b_ih + b_hh
__device__ unsigned g_cnt[8][32];                // per-group barrier counters, 1 per 128B sector

// ---------------- prep: fp32->fp16 weight convert, bias combine, counter reset ----------------
__global__ void prep_kernel(const float* __restrict__ Wih, const float* __restrict__ Whh,
                            const float* __restrict__ bih, const float* __restrict__ bhh) {
    int idx = blockIdx.x * blockDim.x + threadIdx.x;          // grid covers 1048576
    if (idx < GDIM * IDIM) (&g_Wih[0][0])[idx] = __float2half(Wih[idx]);
    if (idx < GDIM * HDIM) (&g_Whh[0][0])[idx] = __float2half(Whh[idx]);
    if (idx < GDIM)        g_bias[idx] = bih[idx] + bhh[idx];
    if (idx < 256)         (&g_cnt[0][0])[idx] = 0u;
}

// ---------------- input projection GEMM: xg[text][s][b][g] = x[b,s,:] @ W_ih[g,:] + bias[g] ----------------
__global__ void __launch_bounds__(256) xgemm_kernel(const float* __restrict__ x0,
                                                    const float* __restrict__ x1) {
    extern __shared__ char sm[];
    half  (*Xs)[72]  = (half (*)[72])sm;                            // 64 x 72 fp16
    half  (*Ws)[72]  = (half (*)[72])(sm + 64 * 72 * 2);            // 256 x 72 fp16
    float (*Os)[260] = (float(*)[260])(sm + 64 * 72 * 2 + 256 * 72 * 2); // 64 x 260 f32

    const int text = blockIdx.z;
    const float* __restrict__ x = text ? x1 : x0;
    const int n0 = blockIdx.x * 256;
    const int rt = blockIdx.y;
    const int s  = rt >> 1;
    const int b0 = (rt & 1) * 64;
    const int tid = threadIdx.x;
    const int w   = tid >> 5;
    const int wm  = (w & 1) * 32;
    const int wn  = (w >> 1) * 64;

    wmma::fragment<wmma::accumulator, 16, 16, 16, float> acc[2][4];
#pragma unroll
    for (int i = 0; i < 2; i++)
#pragma unroll
        for (int j = 0; j < 4; j++) wmma::fill_fragment(acc[i][j], 0.0f);

    for (int kc = 0; kc < IDIM; kc += 64) {
        {
            int r  = tid >> 2;
            int c0 = (tid & 3) * 16;
            const float4* src = (const float4*)(x + (size_t)(b0 + r) * (SEQ * IDIM) + (size_t)s * IDIM + kc + c0);
#pragma unroll
            for (int v = 0; v < 4; v++) {
                float4 f = src[v];
                half2* d = (half2*)&Xs[r][c0 + v * 4];
                d[0] = __floats2half2_rn(f.x, f.y);
                d[1] = __floats2half2_rn(f.z, f.w);
            }
        }
        {
            const uint4* src = (const uint4*)(&g_Wih[n0 + tid][kc]);
            uint4* dst = (uint4*)(&Ws[tid][0]);
#pragma unroll
            for (int v = 0; v < 8; v++) dst[v] = src[v];
        }
        __syncthreads();
#pragma unroll
        for (int kk = 0; kk < 4; kk++) {
            wmma::fragment<wmma::matrix_a, 16, 16, 16, half, wmma::row_major> af[2];
            wmma::load_matrix_sync(af[0], &Xs[wm][kk * 16], 72);
            wmma::load_matrix_sync(af[1], &Xs[wm + 16][kk * 16], 72);
#pragma unroll
            for (int nt = 0; nt < 4; nt++) {
                wmma::fragment<wmma::matrix_b, 16, 16, 16, half, wmma::col_major> bf;
                wmma::load_matrix_sync(bf, &Ws[wn + nt * 16][kk * 16], 72);
                wmma::mma_sync(acc[0][nt], af[0], bf, acc[0][nt]);
                wmma::mma_sync(acc[1][nt], af[1], bf, acc[1][nt]);
            }
        }
        __syncthreads();
    }
#pragma unroll
    for (int i = 0; i < 2; i++)
#pragma unroll
        for (int nt = 0; nt < 4; nt++)
            wmma::store_matrix_sync(&Os[wm + i * 16][wn + nt * 16], acc[i][nt], 260, wmma::mem_row_major);
    __syncthreads();

#pragma unroll
    for (int v = 0; v < 16; v++) {
        int lin = v * 256 + tid;
        int r = lin >> 6;
        int c = (lin & 63) * 4;
        int R = rt * 64 + r;                 // == s*128 + b
        half2 o0 = __floats2half2_rn(Os[r][c + 0] + g_bias[n0 + c + 0],
                                     Os[r][c + 1] + g_bias[n0 + c + 1]);
        half2 o1 = __floats2half2_rn(Os[r][c + 2] + g_bias[n0 + c + 2],
                                     Os[r][c + 3] + g_bias[n0 + c + 3]);
        half2* dst = (half2*)((&g_xg[0][0][0][0]) + ((size_t)text * 65536 + R) * GDIM + n0 + c);
        dst[0] = o0;
        dst[1] = o1;
    }
}

// ---------------- recurrence: 8 independent groups x 16 CTAs, L2 h exchange ----------------
__device__ __forceinline__ uint32_t smem_u32(const void* p) {
    uint32_t a;
    asm("{ .reg .u64 t; cvta.to.shared.u64 t, %1; cvt.u32.u64 %0, t; }" : "=r"(a) : "l"(p));
    return a;
}

__device__ __forceinline__ float fast_sigmoid(float x) {
    return __fdividef(1.0f, 1.0f + __expf(-x));          // MUFU.EX2 + MUFU.RCP path
}
__device__ __forceinline__ float fast_tanh(float x) {
    return 1.0f - __fdividef(2.0f, 1.0f + __expf(2.0f * x));
}

__global__ void __launch_bounds__(256) lstm_rec_kernel(float* __restrict__ out) {
    extern __shared__ char sm[];
    half  (*Wsh)[520] = (half (*)[520])sm;                       // 128 x 520  (133120 B)
    half  (*Ash)[520] = (half (*)[520])(sm + 133120);            // 32 x 520   (33280 B)
    float (*Gsh)[132] = (float(*)[132])(sm + 133120 + 33280);    // 32 x 132   (16896 B)

    const int bx    = blockIdx.x;
    const int text  = bx >> 6;
    const int chunk = (bx >> 4) & 3;
    const int slice = bx & 15;
    const int grp   = bx >> 4;           // 0..7
    const int tid   = threadIdx.x;
    const int w     = tid >> 5;
    const int wm    = (w & 1) * 16;      // warp M offset (0/16)
    const int nq    = w >> 1;            // gate index (0..3), 32 local cols

    // elementwise ownership: each thread owns row b, 4 consecutive cols j0..j0+3
    const int b  = tid >> 3;
    const int j0 = (tid & 7) * 4;
    float creg[4] = {0.f, 0.f, 0.f, 0.f};

    unsigned* const cnt = &g_cnt[grp][0];

    // load persistent W_hh slice: local row r -> global gate row (r>>5)*512 + slice*32 + (r&31)
#pragma unroll
    for (int v = 0; v < 32; v++) {
        int lin = v * 256 + tid;
        int r = lin >> 6, u = lin & 63;
        int grow = (r >> 5) * HDIM + slice * 32 + (r & 31);
        ((uint4*)&Wsh[r][0])[u] = ((const uint4*)&g_Whh[grow][0])[u];
    }
    // zero own h(0) slice in ping 0
    if (tid < 128) {
        int r = tid >> 2, u = tid & 3;
        ((uint2*)&g_h[0][text][chunk * 32 + r][slice * 32])[u] = make_uint2(0, 0);
    }
    __syncthreads();
    if (tid == 0) {
        unsigned one = 1u;
        asm volatile("red.release.gpu.global.add.u32 [%0], %1;" :: "l"(cnt), "r"(one) : "memory");
    }

    unsigned nbar = 1;
    int p = 0;

    for (int t = 0; t < SEQ; t++) {
        // ---- prefetch input-side gates (function of t only; in flight across the wait) ----
        const __half* xbase = &g_xg[text][t][chunk * 32 + b][slice * 32 + j0];
        uint2 xi2 = *(const uint2*)(xbase + 0 * HDIM);
        uint2 xf2 = *(const uint2*)(xbase + 1 * HDIM);
        uint2 xg2 = *(const uint2*)(xbase + 2 * HDIM);
        uint2 xo2 = *(const uint2*)(xbase + 3 * HDIM);

        // ---- per-warp barrier poll: all lanes spin on the counter (one coalesced L2 txn/warp).
        //      Each warp proceeds independently; cross-warp Ash ordering comes from the
        //      wait_group + syncthreads below.
        {
            unsigned tgt = 16u * nbar;
            unsigned v;
            do {
                asm volatile("ld.acquire.gpu.global.u32 %0, [%1];" : "=r"(v) : "l"(cnt) : "memory");
            } while (v < tgt);
        }

        // ---- issue cp.async of full h chunk [32 x 512] as two 16KB commit groups ----
        const __half* hsrc = &g_h[p][text][chunk * 32][0];
#pragma unroll
        for (int half_idx = 0; half_idx < 2; half_idx++) {
#pragma unroll
            for (int it = 0; it < 4; it++) {
                int lin = it * 256 + tid;                      // 0..1023 within this half
                int r = lin >> 5, u = lin & 31;                // row 0..31, 16B-chunk 0..31 (256 cols/half)
                uint32_t dst = smem_u32(&Ash[r][half_idx * 256 + u * 8]);
                const __half* src = hsrc + (size_t)r * HDIM + half_idx * 256 + u * 8;
                asm volatile("cp.async.cg.shared.global [%0], [%1], 16;" :: "r"(dst), "l"(src) : "memory");
            }
            asm volatile("cp.async.commit_group;" ::: "memory");
        }

        // ---- GEMM: gates[32 x 128] = h[32 x 512] @ Whh_slice^T, 2-phase overlap ----
        wmma::fragment<wmma::accumulator, 16, 16, 16, float> accA[2], accB[2];
        wmma::fill_fragment(accA[0], 0.0f); wmma::fill_fragment(accA[1], 0.0f);
        wmma::fill_fragment(accB[0], 0.0f); wmma::fill_fragment(accB[1], 0.0f);

#define GEMM_HALF(HIDX, WG, ACC0, ACC1)                                                    \
        asm volatile("cp.async.wait_group %0;" :: "n"(WG) : "memory");                     \
        __syncthreads();                                                                   \
        _Pragma("unroll")                                                                  \
        for (int kk = (HIDX) * 16; kk < (HIDX) * 16 + 16; kk += 2) {                       \
            wmma::fragment<wmma::matrix_a, 16, 16, 16, half, wmma::row_major> af0, af1;    \
            wmma::load_matrix_sync(af0, &Ash[wm][kk * 16], 520);                           \
            wmma::load_matrix_sync(af1, &Ash[wm][(kk + 1) * 16], 520);                     \
            wmma::fragment<wmma::matrix_b, 16, 16, 16, half, wmma::col_major> bf;          \
            wmma::load_matrix_sync(bf, &Wsh[nq * 32][kk * 16], 520);                       \
            wmma::mma_sync(ACC0[0], af0, bf, ACC0[0]);                                     \
            wmma::load_matrix_sync(bf, &Wsh[nq * 32 + 16][kk * 16], 520);                  \
            wmma::mma_sync(ACC0[1], af0, bf, ACC0[1]);                                     \
            wmma::load_matrix_sync(bf, &Wsh[nq * 32][(kk + 1) * 16], 520);                 \
            wmma::mma_sync(ACC1[0], af1, bf, ACC1[0]);                                     \
            wmma::load_matrix_sync(bf, &Wsh[nq * 32 + 16][(kk + 1) * 16], 520);            \
            wmma::mma_sync(ACC1[1], af1, bf, ACC1[1]);                                     \
        }

        GEMM_HALF(0, 1, accA, accB)
        GEMM_HALF(1, 0, accA, accB)
#undef GEMM_HALF

#pragma unroll
        for (int k = 0; k < 2; k++) {
#pragma unroll
            for (int i = 0; i < accA[k].num_elements; i++) accA[k].x[i] += accB[k].x[i];
        }
        wmma::store_matrix_sync(&Gsh[wm][nq * 32],      accA[0], 132, wmma::mem_row_major);
        wmma::store_matrix_sync(&Gsh[wm][nq * 32 + 16], accA[1], 132, wmma::mem_row_major);
        __syncthreads();

        // ---- gate nonlinearities + state update: 4 cells per thread (b, j0..j0+3) ----
        float4 iv4 = *(const float4*)&Gsh[b][j0];
        float4 fv4 = *(const float4*)&Gsh[b][32 + j0];
        float4 gv4 = *(const float4*)&Gsh[b][64 + j0];
        float4 ov4 = *(const float4*)&Gsh[b][96 + j0];
        float2 xil = __half22float2(*(const half2*)&xi2.x), xih = __half22float2(*(const half2*)&xi2.y);
        float2 xfl = __half22float2(*(const half2*)&xf2.x), xfh = __half22float2(*(const half2*)&xf2.y);
        float2 xgl = __half22float2(*(const half2*)&xg2.x), xgh = __half22float2(*(const half2*)&xg2.y);
        float2 xol = __half22float2(*(const half2*)&xo2.x), xoh = __half22float2(*(const half2*)&xo2.y);

        float iv[4] = {iv4.x + xil.x, iv4.y + xil.y, iv4.z + xih.x, iv4.w + xih.y};
        float fv[4] = {fv4.x + xfl.x, fv4.y + xfl.y, fv4.z + xfh.x, fv4.w + xfh.y};
        float gv[4] = {gv4.x + xgl.x, gv4.y + xgl.y, gv4.z + xgh.x, gv4.w + xgh.y};
        float ov[4] = {ov4.x + xol.x, ov4.y + xol.y, ov4.z + xoh.x, ov4.w + xoh.y};
        float hv[4];
#pragma unroll
        for (int e = 0; e < 4; e++) {
            float i_ = fast_sigmoid(iv[e]);
            float f_ = fast_sigmoid(fv[e]);
            float g_ = fast_tanh(gv[e]);
            float o_ = fast_sigmoid(ov[e]);
            float c  = f_ * creg[e] + i_ * g_;
            creg[e] = c;
            hv[e] = o_ * fast_tanh(c);
        }

        if (t < SEQ - 1) {
            // publish h(t+1) slice (8B store per thread)
            uint2 hp;
            ((half2*)&hp.x)[0] = __floats2half2_rn(hv[0], hv[1]);
            ((half2*)&hp.y)[0] = __floats2half2_rn(hv[2], hv[3]);
            *(uint2*)&g_h[p ^ 1][text][chunk * 32 + b][slice * 32 + j0] = hp;
            __syncthreads();          // all h stores issued before the release
            if (tid == 0) {
                unsigned one = 1u;
                asm volatile("red.release.gpu.global.add.u32 [%0], %1;" :: "l"(cnt), "r"(one) : "memory");
            }
            nbar++;
            p ^= 1;
        } else {
            float4 o4 = make_float4(hv[0], hv[1], hv[2], hv[3]);
            *(float4*)&out[((size_t)text * BATCH + chunk * 32 + b) * HDIM + slice * 32 + j0] = o4;
        }
    }
}

// ---------------- launch ----------------
extern "C" void kernel_launch(void* const* d_in, const int* in_sizes, int n_in,
                              void* d_out, int out_size) {
    (void)in_sizes; (void)n_in; (void)out_size;
    const float* x0  = (const float*)d_in[0];
    const float* x1  = (const float*)d_in[1];
    const float* Wih = (const float*)d_in[2];
    const float* Whh = (const float*)d_in[3];
    const float* bih = (const float*)d_in[4];
    const float* bhh = (const float*)d_in[5];
    float* out = (float*)d_out;

    const int REC_SMEM = 133120 + 33280 + 16896;   // 183296
    cudaFuncSetAttribute(xgemm_kernel,    cudaFuncAttributeMaxDynamicSharedMemorySize, 112640);
    cudaFuncSetAttribute(lstm_rec_kernel, cudaFuncAttributeMaxDynamicSharedMemorySize, REC_SMEM);

    prep_kernel<<<4096, 256>>>(Wih, Whh, bih, bhh);
    xgemm_kernel<<<dim3(8, 1024, 2), 256, 112640>>>(x0, x1);
    lstm_rec_kernel<<<128, 256, REC_SMEM>>>(out);
}